// round 3
// baseline (speedup 1.0000x reference)
#include <cuda_runtime.h>
#include <cuda_bf16.h>

// Problem constants: B=128, N=512, H=512, K=512
#define BB   128
#define NN   512
#define HH   512

// -------------------- scratch (single __device__ buffer, no allocs) -----------
// floats
#define OFF_GX      0L                      // 128*1536
#define OFF_GH      196608L                 // 128*1536
#define OFF_HNEW    393216L                 // 128*512
#define OFF_DENC    458752L
#define OFF_DTGT    524288L
#define OFF_SSTATE  589824L
#define OFF_CPTR    655360L
#define OFF_CTPTR   720896L
#define OFF_CTXE    786432L
#define OFF_CTXT    851968L
#define OFF_SCORE_E 917504L
#define OFF_SCORE_T 983040L
#define OFF_ATTN_E  1048576L
#define OFF_ATTN_T  1114112L
#define OFF_SBIG    1179648L                // 128*512*512 = 33554432
#define SCRATCH_TOTAL (OFF_SBIG + 33554432L)

__device__ float g_scratch[SCRATCH_TOTAL];

// ============================================================================
// Generic tiled fp32 GEMM: C[128 x Ncols] = A[128 x 512] @ B^T
//   B element: Bw[(col)*ldb + bofs + k],  k in [0,512)
//   Tile: BM=128, BN=128, BK=16, 256 threads, 8x8 per-thread micro-tile
// ============================================================================
__global__ void __launch_bounds__(256)
gemm_store_k(const float* __restrict__ A, const float* __restrict__ Bw,
             int ldb, int bofs, float* __restrict__ C, int ldc)
{
    __shared__ float As[16][132];
    __shared__ float Bs[16][132];
    int tid = threadIdx.x;
    int tx = tid & 15, ty = tid >> 4;
    int col0 = blockIdx.x * 128;
    int lr = tid >> 2;
    int lk = (tid & 3) << 2;

    float acc[8][8];
#pragma unroll
    for (int i = 0; i < 8; i++)
#pragma unroll
        for (int j = 0; j < 8; j++) acc[i][j] = 0.f;

    for (int k0 = 0; k0 < 512; k0 += 16) {
        float4 av0 = *(const float4*)(A + (long)lr * 512 + k0 + lk);
        float4 av1 = *(const float4*)(A + (long)(lr + 64) * 512 + k0 + lk);
        float4 bv0 = *(const float4*)(Bw + (long)(col0 + lr) * ldb + bofs + k0 + lk);
        float4 bv1 = *(const float4*)(Bw + (long)(col0 + lr + 64) * ldb + bofs + k0 + lk);
        __syncthreads();
        As[lk + 0][lr] = av0.x; As[lk + 1][lr] = av0.y;
        As[lk + 2][lr] = av0.z; As[lk + 3][lr] = av0.w;
        As[lk + 0][lr + 64] = av1.x; As[lk + 1][lr + 64] = av1.y;
        As[lk + 2][lr + 64] = av1.z; As[lk + 3][lr + 64] = av1.w;
        Bs[lk + 0][lr] = bv0.x; Bs[lk + 1][lr] = bv0.y;
        Bs[lk + 2][lr] = bv0.z; Bs[lk + 3][lr] = bv0.w;
        Bs[lk + 0][lr + 64] = bv1.x; Bs[lk + 1][lr + 64] = bv1.y;
        Bs[lk + 2][lr + 64] = bv1.z; Bs[lk + 3][lr + 64] = bv1.w;
        __syncthreads();
#pragma unroll
        for (int kk = 0; kk < 16; kk++) {
            float a[8], bb[8];
            *(float4*)(a)     = *(const float4*)(&As[kk][ty * 8]);
            *(float4*)(a + 4) = *(const float4*)(&As[kk][ty * 8 + 4]);
            *(float4*)(bb)     = *(const float4*)(&Bs[kk][tx * 8]);
            *(float4*)(bb + 4) = *(const float4*)(&Bs[kk][tx * 8 + 4]);
#pragma unroll
            for (int i = 0; i < 8; i++)
#pragma unroll
                for (int j = 0; j < 8; j++) acc[i][j] += a[i] * bb[j];
        }
    }
#pragma unroll
    for (int i = 0; i < 8; i++) {
        int row = ty * 8 + i;
        float4 o0 = make_float4(acc[i][0], acc[i][1], acc[i][2], acc[i][3]);
        float4 o1 = make_float4(acc[i][4], acc[i][5], acc[i][6], acc[i][7]);
        *(float4*)(C + (long)row * ldc + col0 + tx * 8) = o0;
        *(float4*)(C + (long)row * ldc + col0 + tx * 8 + 4) = o1;
    }
}

// ============================================================================
// Big fused GEMM over static_hidden (65536 x 512) x [enc_Ws | tgt_Ws | ptr_Ws]
//   g==0: enc scores epilogue (tanh + dot v_enc)   -> score_e[row]
//   g==1: tgt scores epilogue                      -> score_t[row]
//   g==2: store S_ptr tile                         -> Sbig[row][h]
// No atomics: each block covers the full 512 h-range of its group.
// ============================================================================
__global__ void __launch_bounds__(256)
big_fused_k(const float* __restrict__ stat,
            const float* __restrict__ encW, const float* __restrict__ tgtW,
            const float* __restrict__ ptrW,
            const float* __restrict__ encv, const float* __restrict__ tgtv,
            const float* __restrict__ denc, const float* __restrict__ dtgt,
            float* __restrict__ score_e, float* __restrict__ score_t,
            float* __restrict__ Sbig)
{
    __shared__ float As[16][132];
    __shared__ float Bs[16][132];
    int tid = threadIdx.x;
    int tx = tid & 15, ty = tid >> 4;
    int row0 = blockIdx.x * 128;
    int g = blockIdx.y;
    int b = row0 >> 9;
    const float* A = stat + (long)row0 * 512;
    const float* Bw  = (g == 0) ? encW : (g == 1) ? tgtW : ptrW;
    long ldb         = (g == 2) ? 1536 : 1024;
    const float* dvec = (g == 0) ? denc : dtgt;
    const float* vv   = (g == 0) ? encv : tgtv;
    int lr = tid >> 2;
    int lk = (tid & 3) << 2;

    float sacc[8];
#pragma unroll
    for (int i = 0; i < 8; i++) sacc[i] = 0.f;

    for (int ht = 0; ht < 4; ht++) {
        int col0 = ht * 128;
        float acc[8][8];
#pragma unroll
        for (int i = 0; i < 8; i++)
#pragma unroll
            for (int j = 0; j < 8; j++) acc[i][j] = 0.f;

        for (int k0 = 0; k0 < 512; k0 += 16) {
            float4 av0 = *(const float4*)(A + (long)lr * 512 + k0 + lk);
            float4 av1 = *(const float4*)(A + (long)(lr + 64) * 512 + k0 + lk);
            float4 bv0 = *(const float4*)(Bw + (long)(col0 + lr) * ldb + k0 + lk);
            float4 bv1 = *(const float4*)(Bw + (long)(col0 + lr + 64) * ldb + k0 + lk);
            __syncthreads();
            As[lk + 0][lr] = av0.x; As[lk + 1][lr] = av0.y;
            As[lk + 2][lr] = av0.z; As[lk + 3][lr] = av0.w;
            As[lk + 0][lr + 64] = av1.x; As[lk + 1][lr + 64] = av1.y;
            As[lk + 2][lr + 64] = av1.z; As[lk + 3][lr + 64] = av1.w;
            Bs[lk + 0][lr] = bv0.x; Bs[lk + 1][lr] = bv0.y;
            Bs[lk + 2][lr] = bv0.z; Bs[lk + 3][lr] = bv0.w;
            Bs[lk + 0][lr + 64] = bv1.x; Bs[lk + 1][lr + 64] = bv1.y;
            Bs[lk + 2][lr + 64] = bv1.z; Bs[lk + 3][lr + 64] = bv1.w;
            __syncthreads();
#pragma unroll
            for (int kk = 0; kk < 16; kk++) {
                float a[8], bb[8];
                *(float4*)(a)     = *(const float4*)(&As[kk][ty * 8]);
                *(float4*)(a + 4) = *(const float4*)(&As[kk][ty * 8 + 4]);
                *(float4*)(bb)     = *(const float4*)(&Bs[kk][tx * 8]);
                *(float4*)(bb + 4) = *(const float4*)(&Bs[kk][tx * 8 + 4]);
#pragma unroll
                for (int i = 0; i < 8; i++)
#pragma unroll
                    for (int j = 0; j < 8; j++) acc[i][j] += a[i] * bb[j];
            }
        }

        if (g < 2) {
#pragma unroll
            for (int j = 0; j < 8; j++) {
                int h = col0 + tx * 8 + j;
                float vj = vv[h];
                float dj = dvec[b * 512 + h];
#pragma unroll
                for (int i = 0; i < 8; i++)
                    sacc[i] += vj * tanhf(acc[i][j] + dj);
            }
        } else {
#pragma unroll
            for (int i = 0; i < 8; i++) {
                long base = ((long)(row0 + ty * 8 + i)) * 512 + col0 + tx * 8;
                *(float4*)(Sbig + base)     = make_float4(acc[i][0], acc[i][1], acc[i][2], acc[i][3]);
                *(float4*)(Sbig + base + 4) = make_float4(acc[i][4], acc[i][5], acc[i][6], acc[i][7]);
            }
        }
    }

    if (g < 2) {
        float* o = (g == 0) ? score_e : score_t;
#pragma unroll
        for (int i = 0; i < 8; i++) {
            float s = sacc[i];
            s += __shfl_xor_sync(0xffffffffu, s, 1);
            s += __shfl_xor_sync(0xffffffffu, s, 2);
            s += __shfl_xor_sync(0xffffffffu, s, 4);
            s += __shfl_xor_sync(0xffffffffu, s, 8);
            if (tx == 0) o[row0 + ty * 8 + i] = s;   // exactly one writer -> deterministic
        }
    }
}

// ============================================================================
// GRU gates: h_new = (1-z)*n + z*h
// ============================================================================
__global__ void gru_gates_k(const float* __restrict__ gx, const float* __restrict__ gh,
                            const float* __restrict__ bih, const float* __restrict__ bhh,
                            const float* __restrict__ lhh,
                            float* __restrict__ hnew, float* __restrict__ outh)
{
    int i = blockIdx.x * blockDim.x + threadIdx.x;   // 65536
    int b = i >> 9, j = i & 511;
    const float* gxb = gx + b * 1536;
    const float* ghb = gh + b * 1536;
    float xr = gxb[j] + bih[j],              hr = ghb[j] + bhh[j];
    float xz = gxb[512 + j] + bih[512 + j],  hz = ghb[512 + j] + bhh[512 + j];
    float xn = gxb[1024 + j] + bih[1024 + j];
    float hn = ghb[1024 + j] + bhh[1024 + j];
    float r = 1.f / (1.f + expf(-(xr + hr)));
    float z = 1.f / (1.f + expf(-(xz + hz)));
    float n = tanhf(xn + r * hn);
    float h = lhh[i];
    float v = (1.f - z) * n + z * h;
    hnew[i] = v;
    outh[i] = v;
}

// ============================================================================
// Softmax over n (512) per batch; blockIdx.x in [0,256): low 7 bits = b, bit7 = which
// ============================================================================
__global__ void softmax_k(const float* __restrict__ score_e, const float* __restrict__ score_t,
                          float* __restrict__ attn_e, float* __restrict__ attn_t)
{
    int b = blockIdx.x & 127;
    int wh = blockIdx.x >> 7;
    const float* src = (wh ? score_t : score_e) + b * 512;
    float* dst = (wh ? attn_t : attn_e) + b * 512;
    int t = threadIdx.x;
    float v0 = src[t], v1 = src[t + 256];
    __shared__ float red[256];
    red[t] = fmaxf(v0, v1);
    __syncthreads();
    for (int s = 128; s > 0; s >>= 1) {
        if (t < s) red[t] = fmaxf(red[t], red[t + s]);
        __syncthreads();
    }
    float mx = red[0];
    __syncthreads();
    float e0 = expf(v0 - mx), e1 = expf(v1 - mx);
    red[t] = e0 + e1;
    __syncthreads();
    for (int s = 128; s > 0; s >>= 1) {
        if (t < s) red[t] += red[t + s];
        __syncthreads();
    }
    float inv = 1.f / red[0];
    dst[t] = e0 * inv;
    dst[t + 256] = e1 * inv;
}

// ============================================================================
// Both contexts in one pass over static_hidden
// ============================================================================
__global__ void context_k(const float* __restrict__ stat,
                          const float* __restrict__ ae, const float* __restrict__ at,
                          float* __restrict__ ce, float* __restrict__ ct)
{
    int b = blockIdx.x >> 2;
    int ch = blockIdx.x & 3;
    int h = ch * 128 + threadIdx.x;
    __shared__ float sae[512], sat[512];
    for (int i = threadIdx.x; i < 512; i += 128) {
        sae[i] = ae[b * 512 + i];
        sat[i] = at[b * 512 + i];
    }
    __syncthreads();
    const float* Sb = stat + (long)b * 262144 + h;
    float se = 0.f, st = 0.f;
#pragma unroll 8
    for (int n = 0; n < 512; n++) {
        float sv = Sb[(long)n * 512];
        se += sae[n] * sv;
        st += sat[n] * sv;
    }
    ce[b * 512 + h] = se;
    ct[b * 512 + h] = st;
}

// ============================================================================
// Final pointer scores: probs = 5*ptr(context) + ptr(context_t); one warp per (b,n)
// ============================================================================
__global__ void final_k(const float* __restrict__ Sbig,
                        const float* __restrict__ cp, const float* __restrict__ ctp,
                        const float* __restrict__ ss, const float* __restrict__ vp,
                        float* __restrict__ out)
{
    int w = (blockIdx.x * blockDim.x + threadIdx.x) >> 5;   // 65536 warps
    int lane = threadIdx.x & 31;
    int b = w >> 9;
    const float* Sp = Sbig + (long)w * 512;
    const float* c1 = cp + b * 512;
    const float* c2 = ctp + b * 512;
    const float* s0 = ss + b * 512;
    float s1 = 0.f, s2 = 0.f;
    for (int k = lane; k < 512; k += 32) {
        float x = Sp[k];
        float v = vp[k];
        float a = s0[k];
        s1 += v * tanhf(x + c1[k] + a);
        s2 += v * tanhf(x + c2[k] + a);
    }
    for (int o = 16; o > 0; o >>= 1) {
        s1 += __shfl_xor_sync(0xffffffffu, s1, o);
        s2 += __shfl_xor_sync(0xffffffffu, s2, o);
    }
    if (lane == 0) out[w] = 5.0f * s1 + s2;
}

// ============================================================================
extern "C" void kernel_launch(void* const* d_in, const int* in_sizes, int n_in,
                              void* d_out, int out_size)
{
    const float* stat = (const float*)d_in[0];   // static_hidden (128,512,512)
    const float* semb = (const float*)d_in[1];   // state_embedding (128,1,512)
    const float* dech = (const float*)d_in[2];   // decoder_hidden (128,1,512)
    const float* tgth = (const float*)d_in[3];   // target_hidden (128,1,512)
    const float* lhh  = (const float*)d_in[4];   // last_hh (1,128,512)
    const float* ptrv = (const float*)d_in[5];   // (1,1,512)
    const float* ptrW = (const float*)d_in[6];   // (1,512,1536)
    const float* encv = (const float*)d_in[7];   // (1,1,512)
    const float* encW = (const float*)d_in[8];   // (1,512,1024)
    const float* tgtv = (const float*)d_in[9];   // (1,1,512)
    const float* tgtW = (const float*)d_in[10];  // (1,512,1024)
    const float* wih  = (const float*)d_in[11];  // (1536,512)
    const float* whh  = (const float*)d_in[12];  // (1536,512)
    const float* bih  = (const float*)d_in[13];  // (1536,)
    const float* bhh  = (const float*)d_in[14];  // (1536,)
    float* out = (float*)d_out;                  // [probs 65536 | new_last_hh 65536]

    float* S = nullptr;
    cudaGetSymbolAddress((void**)&S, g_scratch);
    float* gx     = S + OFF_GX;
    float* gh     = S + OFF_GH;
    float* hnew   = S + OFF_HNEW;
    float* denc   = S + OFF_DENC;
    float* dtgt   = S + OFF_DTGT;
    float* sstate = S + OFF_SSTATE;
    float* cptr   = S + OFF_CPTR;
    float* ctptr  = S + OFF_CTPTR;
    float* ctxe   = S + OFF_CTXE;
    float* ctxt   = S + OFF_CTXT;
    float* sc_e   = S + OFF_SCORE_E;
    float* sc_t   = S + OFF_SCORE_T;
    float* at_e   = S + OFF_ATTN_E;
    float* at_t   = S + OFF_ATTN_T;
    float* Sbig   = S + OFF_SBIG;

    // 1) GRU input/hidden GEMMs: gx = x @ w_ih^T, gh = h @ w_hh^T
    gemm_store_k<<<12, 256>>>(dech, wih, 512, 0, gx, 1536);
    gemm_store_k<<<12, 256>>>(lhh,  whh, 512, 0, gh, 1536);

    // 2) GRU gates -> h_new (also second half of output)
    gru_gates_k<<<256, 256>>>(gx, gh, bih, bhh, lhh, hnew, out + 65536);

    // 3) Per-batch bias projections
    gemm_store_k<<<4, 256>>>(hnew, encW, 1024, 512,  denc,   512);  // h_new @ enc_Wd^T
    gemm_store_k<<<4, 256>>>(tgth, tgtW, 1024, 512,  dtgt,   512);  // target @ tgt_Wd^T
    gemm_store_k<<<4, 256>>>(semb, ptrW, 1536, 1024, sstate, 512);  // state  @ ptr_We^T

    // 4) Big fused GEMM: enc scores, tgt scores, S_ptr
    big_fused_k<<<dim3(512, 3), 256>>>(stat, encW, tgtW, ptrW, encv, tgtv,
                                       denc, dtgt, sc_e, sc_t, Sbig);

    // 5) Softmaxes
    softmax_k<<<256, 256>>>(sc_e, sc_t, at_e, at_t);

    // 6) Contexts (both in one pass)
    context_k<<<512, 128>>>(stat, at_e, at_t, ctxe, ctxt);

    // 7) Context projections through ptr_W context slice
    gemm_store_k<<<4, 256>>>(ctxe, ptrW, 1536, 512, cptr,  512);
    gemm_store_k<<<4, 256>>>(ctxt, ptrW, 1536, 512, ctptr, 512);

    // 8) Final pointer scores -> probs
    final_k<<<8192, 256>>>(Sbig, cptr, ctptr, sstate, ptrv, out);
}

// round 4
// speedup vs baseline: 1.0036x; 1.0036x over previous
#include <cuda_runtime.h>
#include <cuda_bf16.h>

// Problem constants: B=128, N=512, H=512, K=512
#define BB   128
#define NN   512
#define HH   512

// -------------------- scratch (single __device__ buffer, no allocs) -----------
// floats
#define OFF_GX      0L                      // 128*1536
#define OFF_GH      196608L                 // 128*1536
#define OFF_HNEW    393216L                 // 128*512
#define OFF_DENC    458752L
#define OFF_DTGT    524288L
#define OFF_SSTATE  589824L
#define OFF_CPTR    655360L
#define OFF_CTPTR   720896L
#define OFF_CTXE    786432L
#define OFF_CTXT    851968L
#define OFF_SCORE_E 917504L
#define OFF_SCORE_T 983040L
#define OFF_ATTN_E  1048576L
#define OFF_ATTN_T  1114112L
#define OFF_SBIG    1179648L                // 128*512*512 = 33554432
#define SCRATCH_TOTAL (OFF_SBIG + 33554432L)

__device__ float g_scratch[SCRATCH_TOTAL];

// ============================================================================
// Generic tiled fp32 GEMM: C[128 x Ncols] = A[128 x 512] @ B^T
//   B element: Bw[(col)*ldb + bofs + k],  k in [0,512)
//   Tile: BM=128, BN=128, BK=16, 256 threads, 8x8 per-thread micro-tile
// ============================================================================
__global__ void __launch_bounds__(256)
gemm_store_k(const float* __restrict__ A, const float* __restrict__ Bw,
             int ldb, int bofs, float* __restrict__ C, int ldc)
{
    __shared__ float As[16][132];
    __shared__ float Bs[16][132];
    int tid = threadIdx.x;
    int tx = tid & 15, ty = tid >> 4;
    int col0 = blockIdx.x * 128;
    int lr = tid >> 2;
    int lk = (tid & 3) << 2;

    float acc[8][8];
#pragma unroll
    for (int i = 0; i < 8; i++)
#pragma unroll
        for (int j = 0; j < 8; j++) acc[i][j] = 0.f;

    for (int k0 = 0; k0 < 512; k0 += 16) {
        float4 av0 = *(const float4*)(A + (long)lr * 512 + k0 + lk);
        float4 av1 = *(const float4*)(A + (long)(lr + 64) * 512 + k0 + lk);
        float4 bv0 = *(const float4*)(Bw + (long)(col0 + lr) * ldb + bofs + k0 + lk);
        float4 bv1 = *(const float4*)(Bw + (long)(col0 + lr + 64) * ldb + bofs + k0 + lk);
        __syncthreads();
        As[lk + 0][lr] = av0.x; As[lk + 1][lr] = av0.y;
        As[lk + 2][lr] = av0.z; As[lk + 3][lr] = av0.w;
        As[lk + 0][lr + 64] = av1.x; As[lk + 1][lr + 64] = av1.y;
        As[lk + 2][lr + 64] = av1.z; As[lk + 3][lr + 64] = av1.w;
        Bs[lk + 0][lr] = bv0.x; Bs[lk + 1][lr] = bv0.y;
        Bs[lk + 2][lr] = bv0.z; Bs[lk + 3][lr] = bv0.w;
        Bs[lk + 0][lr + 64] = bv1.x; Bs[lk + 1][lr + 64] = bv1.y;
        Bs[lk + 2][lr + 64] = bv1.z; Bs[lk + 3][lr + 64] = bv1.w;
        __syncthreads();
#pragma unroll
        for (int kk = 0; kk < 16; kk++) {
            float a[8], bb[8];
            *(float4*)(a)     = *(const float4*)(&As[kk][ty * 8]);
            *(float4*)(a + 4) = *(const float4*)(&As[kk][ty * 8 + 4]);
            *(float4*)(bb)     = *(const float4*)(&Bs[kk][tx * 8]);
            *(float4*)(bb + 4) = *(const float4*)(&Bs[kk][tx * 8 + 4]);
#pragma unroll
            for (int i = 0; i < 8; i++)
#pragma unroll
                for (int j = 0; j < 8; j++) acc[i][j] += a[i] * bb[j];
        }
    }
#pragma unroll
    for (int i = 0; i < 8; i++) {
        int row = ty * 8 + i;
        float4 o0 = make_float4(acc[i][0], acc[i][1], acc[i][2], acc[i][3]);
        float4 o1 = make_float4(acc[i][4], acc[i][5], acc[i][6], acc[i][7]);
        *(float4*)(C + (long)row * ldc + col0 + tx * 8) = o0;
        *(float4*)(C + (long)row * ldc + col0 + tx * 8 + 4) = o1;
    }
}

// ============================================================================
// Big fused GEMM over static_hidden (65536 x 512) x [enc_Ws | tgt_Ws | ptr_Ws]
//   g==0: enc scores epilogue (tanh + dot v_enc)   -> score_e[row]
//   g==1: tgt scores epilogue                      -> score_t[row]
//   g==2: store S_ptr tile                         -> Sbig[row][h]
// No atomics: each block covers the full 512 h-range of its group.
// ============================================================================
__global__ void __launch_bounds__(256)
big_fused_k(const float* __restrict__ stat,
            const float* __restrict__ encW, const float* __restrict__ tgtW,
            const float* __restrict__ ptrW,
            const float* __restrict__ encv, const float* __restrict__ tgtv,
            const float* __restrict__ denc, const float* __restrict__ dtgt,
            float* __restrict__ score_e, float* __restrict__ score_t,
            float* __restrict__ Sbig)
{
    __shared__ float As[16][132];
    __shared__ float Bs[16][132];
    int tid = threadIdx.x;
    int tx = tid & 15, ty = tid >> 4;
    int row0 = blockIdx.x * 128;
    int g = blockIdx.y;
    int b = row0 >> 9;
    const float* A = stat + (long)row0 * 512;
    const float* Bw  = (g == 0) ? encW : (g == 1) ? tgtW : ptrW;
    long ldb         = (g == 2) ? 1536 : 1024;
    const float* dvec = (g == 0) ? denc : dtgt;
    const float* vv   = (g == 0) ? encv : tgtv;
    int lr = tid >> 2;
    int lk = (tid & 3) << 2;

    float sacc[8];
#pragma unroll
    for (int i = 0; i < 8; i++) sacc[i] = 0.f;

    for (int ht = 0; ht < 4; ht++) {
        int col0 = ht * 128;
        float acc[8][8];
#pragma unroll
        for (int i = 0; i < 8; i++)
#pragma unroll
            for (int j = 0; j < 8; j++) acc[i][j] = 0.f;

        for (int k0 = 0; k0 < 512; k0 += 16) {
            float4 av0 = *(const float4*)(A + (long)lr * 512 + k0 + lk);
            float4 av1 = *(const float4*)(A + (long)(lr + 64) * 512 + k0 + lk);
            float4 bv0 = *(const float4*)(Bw + (long)(col0 + lr) * ldb + k0 + lk);
            float4 bv1 = *(const float4*)(Bw + (long)(col0 + lr + 64) * ldb + k0 + lk);
            __syncthreads();
            As[lk + 0][lr] = av0.x; As[lk + 1][lr] = av0.y;
            As[lk + 2][lr] = av0.z; As[lk + 3][lr] = av0.w;
            As[lk + 0][lr + 64] = av1.x; As[lk + 1][lr + 64] = av1.y;
            As[lk + 2][lr + 64] = av1.z; As[lk + 3][lr + 64] = av1.w;
            Bs[lk + 0][lr] = bv0.x; Bs[lk + 1][lr] = bv0.y;
            Bs[lk + 2][lr] = bv0.z; Bs[lk + 3][lr] = bv0.w;
            Bs[lk + 0][lr + 64] = bv1.x; Bs[lk + 1][lr + 64] = bv1.y;
            Bs[lk + 2][lr + 64] = bv1.z; Bs[lk + 3][lr + 64] = bv1.w;
            __syncthreads();
#pragma unroll
            for (int kk = 0; kk < 16; kk++) {
                float a[8], bb[8];
                *(float4*)(a)     = *(const float4*)(&As[kk][ty * 8]);
                *(float4*)(a + 4) = *(const float4*)(&As[kk][ty * 8 + 4]);
                *(float4*)(bb)     = *(const float4*)(&Bs[kk][tx * 8]);
                *(float4*)(bb + 4) = *(const float4*)(&Bs[kk][tx * 8 + 4]);
#pragma unroll
                for (int i = 0; i < 8; i++)
#pragma unroll
                    for (int j = 0; j < 8; j++) acc[i][j] += a[i] * bb[j];
            }
        }

        if (g < 2) {
#pragma unroll
            for (int j = 0; j < 8; j++) {
                int h = col0 + tx * 8 + j;
                float vj = vv[h];
                float dj = dvec[b * 512 + h];
#pragma unroll
                for (int i = 0; i < 8; i++)
                    sacc[i] += vj * tanhf(acc[i][j] + dj);
            }
        } else {
#pragma unroll
            for (int i = 0; i < 8; i++) {
                long base = ((long)(row0 + ty * 8 + i)) * 512 + col0 + tx * 8;
                *(float4*)(Sbig + base)     = make_float4(acc[i][0], acc[i][1], acc[i][2], acc[i][3]);
                *(float4*)(Sbig + base + 4) = make_float4(acc[i][4], acc[i][5], acc[i][6], acc[i][7]);
            }
        }
    }

    if (g < 2) {
        float* o = (g == 0) ? score_e : score_t;
#pragma unroll
        for (int i = 0; i < 8; i++) {
            float s = sacc[i];
            s += __shfl_xor_sync(0xffffffffu, s, 1);
            s += __shfl_xor_sync(0xffffffffu, s, 2);
            s += __shfl_xor_sync(0xffffffffu, s, 4);
            s += __shfl_xor_sync(0xffffffffu, s, 8);
            if (tx == 0) o[row0 + ty * 8 + i] = s;   // exactly one writer -> deterministic
        }
    }
}

// ============================================================================
// GRU gates: h_new = (1-z)*n + z*h
// ============================================================================
__global__ void gru_gates_k(const float* __restrict__ gx, const float* __restrict__ gh,
                            const float* __restrict__ bih, const float* __restrict__ bhh,
                            const float* __restrict__ lhh,
                            float* __restrict__ hnew, float* __restrict__ outh)
{
    int i = blockIdx.x * blockDim.x + threadIdx.x;   // 65536
    int b = i >> 9, j = i & 511;
    const float* gxb = gx + b * 1536;
    const float* ghb = gh + b * 1536;
    float xr = gxb[j] + bih[j],              hr = ghb[j] + bhh[j];
    float xz = gxb[512 + j] + bih[512 + j],  hz = ghb[512 + j] + bhh[512 + j];
    float xn = gxb[1024 + j] + bih[1024 + j];
    float hn = ghb[1024 + j] + bhh[1024 + j];
    float r = 1.f / (1.f + expf(-(xr + hr)));
    float z = 1.f / (1.f + expf(-(xz + hz)));
    float n = tanhf(xn + r * hn);
    float h = lhh[i];
    float v = (1.f - z) * n + z * h;
    hnew[i] = v;
    outh[i] = v;
}

// ============================================================================
// Softmax over n (512) per batch; blockIdx.x in [0,256): low 7 bits = b, bit7 = which
// ============================================================================
__global__ void softmax_k(const float* __restrict__ score_e, const float* __restrict__ score_t,
                          float* __restrict__ attn_e, float* __restrict__ attn_t)
{
    int b = blockIdx.x & 127;
    int wh = blockIdx.x >> 7;
    const float* src = (wh ? score_t : score_e) + b * 512;
    float* dst = (wh ? attn_t : attn_e) + b * 512;
    int t = threadIdx.x;
    float v0 = src[t], v1 = src[t + 256];
    __shared__ float red[256];
    red[t] = fmaxf(v0, v1);
    __syncthreads();
    for (int s = 128; s > 0; s >>= 1) {
        if (t < s) red[t] = fmaxf(red[t], red[t + s]);
        __syncthreads();
    }
    float mx = red[0];
    __syncthreads();
    float e0 = expf(v0 - mx), e1 = expf(v1 - mx);
    red[t] = e0 + e1;
    __syncthreads();
    for (int s = 128; s > 0; s >>= 1) {
        if (t < s) red[t] += red[t + s];
        __syncthreads();
    }
    float inv = 1.f / red[0];
    dst[t] = e0 * inv;
    dst[t + 256] = e1 * inv;
}

// ============================================================================
// Both contexts in one pass over static_hidden
// ============================================================================
__global__ void context_k(const float* __restrict__ stat,
                          const float* __restrict__ ae, const float* __restrict__ at,
                          float* __restrict__ ce, float* __restrict__ ct)
{
    int b = blockIdx.x >> 2;
    int ch = blockIdx.x & 3;
    int h = ch * 128 + threadIdx.x;
    __shared__ float sae[512], sat[512];
    for (int i = threadIdx.x; i < 512; i += 128) {
        sae[i] = ae[b * 512 + i];
        sat[i] = at[b * 512 + i];
    }
    __syncthreads();
    const float* Sb = stat + (long)b * 262144 + h;
    float se = 0.f, st = 0.f;
#pragma unroll 8
    for (int n = 0; n < 512; n++) {
        float sv = Sb[(long)n * 512];
        se += sae[n] * sv;
        st += sat[n] * sv;
    }
    ce[b * 512 + h] = se;
    ct[b * 512 + h] = st;
}

// ============================================================================
// Final pointer scores: probs = 5*ptr(context) + ptr(context_t); one warp per (b,n)
// ============================================================================
__global__ void final_k(const float* __restrict__ Sbig,
                        const float* __restrict__ cp, const float* __restrict__ ctp,
                        const float* __restrict__ ss, const float* __restrict__ vp,
                        float* __restrict__ out)
{
    int w = (blockIdx.x * blockDim.x + threadIdx.x) >> 5;   // 65536 warps
    int lane = threadIdx.x & 31;
    int b = w >> 9;
    const float* Sp = Sbig + (long)w * 512;
    const float* c1 = cp + b * 512;
    const float* c2 = ctp + b * 512;
    const float* s0 = ss + b * 512;
    float s1 = 0.f, s2 = 0.f;
    for (int k = lane; k < 512; k += 32) {
        float x = Sp[k];
        float v = vp[k];
        float a = s0[k];
        s1 += v * tanhf(x + c1[k] + a);
        s2 += v * tanhf(x + c2[k] + a);
    }
    for (int o = 16; o > 0; o >>= 1) {
        s1 += __shfl_xor_sync(0xffffffffu, s1, o);
        s2 += __shfl_xor_sync(0xffffffffu, s2, o);
    }
    if (lane == 0) out[w] = 5.0f * s1 + s2;
}

// ============================================================================
extern "C" void kernel_launch(void* const* d_in, const int* in_sizes, int n_in,
                              void* d_out, int out_size)
{
    const float* stat = (const float*)d_in[0];   // static_hidden (128,512,512)
    const float* semb = (const float*)d_in[1];   // state_embedding (128,1,512)
    const float* dech = (const float*)d_in[2];   // decoder_hidden (128,1,512)
    const float* tgth = (const float*)d_in[3];   // target_hidden (128,1,512)
    const float* lhh  = (const float*)d_in[4];   // last_hh (1,128,512)
    const float* ptrv = (const float*)d_in[5];   // (1,1,512)
    const float* ptrW = (const float*)d_in[6];   // (1,512,1536)
    const float* encv = (const float*)d_in[7];   // (1,1,512)
    const float* encW = (const float*)d_in[8];   // (1,512,1024)
    const float* tgtv = (const float*)d_in[9];   // (1,1,512)
    const float* tgtW = (const float*)d_in[10];  // (1,512,1024)
    const float* wih  = (const float*)d_in[11];  // (1536,512)
    const float* whh  = (const float*)d_in[12];  // (1536,512)
    const float* bih  = (const float*)d_in[13];  // (1536,)
    const float* bhh  = (const float*)d_in[14];  // (1536,)
    float* out = (float*)d_out;                  // [probs 65536 | new_last_hh 65536]

    float* S = nullptr;
    cudaGetSymbolAddress((void**)&S, g_scratch);
    float* gx     = S + OFF_GX;
    float* gh     = S + OFF_GH;
    float* hnew   = S + OFF_HNEW;
    float* denc   = S + OFF_DENC;
    float* dtgt   = S + OFF_DTGT;
    float* sstate = S + OFF_SSTATE;
    float* cptr   = S + OFF_CPTR;
    float* ctptr  = S + OFF_CTPTR;
    float* ctxe   = S + OFF_CTXE;
    float* ctxt   = S + OFF_CTXT;
    float* sc_e   = S + OFF_SCORE_E;
    float* sc_t   = S + OFF_SCORE_T;
    float* at_e   = S + OFF_ATTN_E;
    float* at_t   = S + OFF_ATTN_T;
    float* Sbig   = S + OFF_SBIG;

    // 1) GRU input/hidden GEMMs: gx = x @ w_ih^T, gh = h @ w_hh^T
    gemm_store_k<<<12, 256>>>(dech, wih, 512, 0, gx, 1536);
    gemm_store_k<<<12, 256>>>(lhh,  whh, 512, 0, gh, 1536);

    // 2) GRU gates -> h_new (also second half of output)
    gru_gates_k<<<256, 256>>>(gx, gh, bih, bhh, lhh, hnew, out + 65536);

    // 3) Per-batch bias projections
    gemm_store_k<<<4, 256>>>(hnew, encW, 1024, 512,  denc,   512);  // h_new @ enc_Wd^T
    gemm_store_k<<<4, 256>>>(tgth, tgtW, 1024, 512,  dtgt,   512);  // target @ tgt_Wd^T
    gemm_store_k<<<4, 256>>>(semb, ptrW, 1536, 1024, sstate, 512);  // state  @ ptr_We^T

    // 4) Big fused GEMM: enc scores, tgt scores, S_ptr
    big_fused_k<<<dim3(512, 3), 256>>>(stat, encW, tgtW, ptrW, encv, tgtv,
                                       denc, dtgt, sc_e, sc_t, Sbig);

    // 5) Softmaxes
    softmax_k<<<256, 256>>>(sc_e, sc_t, at_e, at_t);

    // 6) Contexts (both in one pass)
    context_k<<<512, 128>>>(stat, at_e, at_t, ctxe, ctxt);

    // 7) Context projections through ptr_W context slice
    gemm_store_k<<<4, 256>>>(ctxe, ptrW, 1536, 512, cptr,  512);
    gemm_store_k<<<4, 256>>>(ctxt, ptrW, 1536, 512, ctptr, 512);

    // 8) Final pointer scores -> probs
    final_k<<<8192, 256>>>(Sbig, cptr, ctptr, sstate, ptrv, out);
}

// round 7
// speedup vs baseline: 1.7307x; 1.7244x over previous
#include <cuda_runtime.h>
#include <cuda_bf16.h>

// ===========================================================================
// B=128, N=512, H=512.  Output: [probs 65536 | new_last_hh 65536] fp32
// Big GEMM on tensor cores via mma.sync bf16 (sm_103-safe, no tcgen05).
// ===========================================================================

// -------------------- scratch (byte offsets) --------------------------------
#define OFF_SBIGT  0L                       // 512*65536 f32 (S_ptr, [h][row])
#define OFF_SHI    134217728L               // stat hi bf16 [65536][512]
#define OFF_SLO    201326592L               // stat lo bf16
#define OFF_BHI    268435456L               // Bcat hi bf16 [1536][512]
#define OFF_BLO    270008320L
#define OFF_FL     271581184L               // float region
#define SCRATCH_BYTES (OFF_FL + 4718592L)
__device__ __align__(1024) unsigned char g_scratch[SCRATCH_BYTES];

// float sub-offsets (in floats) inside FL region
#define FO_GX     0L
#define FO_GH     196608L
#define FO_HNEW   393216L
#define FO_DENC   458752L
#define FO_DTGT   524288L
#define FO_SSTATE 589824L
#define FO_CPTR   655360L
#define FO_CTPTR  720896L
#define FO_CTXE   786432L
#define FO_CTXT   851968L
#define FO_SCE    917504L
#define FO_SCT    983040L
#define FO_ATE    1048576L
#define FO_ATT    1114112L

// ===================== PTX helpers (baseline ISA only) ======================
__device__ __forceinline__ unsigned smem_u32(const void* p) {
    unsigned a;
    asm("{ .reg .u64 t; cvta.to.shared.u64 t, %1; cvt.u32.u64 %0, t; }"
        : "=r"(a) : "l"(p));
    return a;
}
__device__ __forceinline__ void cp16(unsigned dst, const void* src) {
    asm volatile("cp.async.cg.shared.global [%0], [%1], 16;" :: "r"(dst), "l"(src));
}
#define CP_COMMIT() asm volatile("cp.async.commit_group;" ::: "memory")
#define CP_WAIT1()  asm volatile("cp.async.wait_group 1;" ::: "memory")
#define CP_WAIT0()  asm volatile("cp.async.wait_group 0;" ::: "memory")

__device__ __forceinline__ void mma16816(float c[4],
        unsigned a0, unsigned a1, unsigned a2, unsigned a3,
        unsigned b0, unsigned b1) {
    asm volatile(
        "mma.sync.aligned.m16n8k16.row.col.f32.bf16.bf16.f32 "
        "{%0,%1,%2,%3}, {%4,%5,%6,%7}, {%8,%9}, {%0,%1,%2,%3};"
        : "+f"(c[0]), "+f"(c[1]), "+f"(c[2]), "+f"(c[3])
        : "r"(a0), "r"(a1), "r"(a2), "r"(a3), "r"(b0), "r"(b1));
}

// ===========================================================================
// fp32 -> (bf16 hi, bf16 lo) conversions
// ===========================================================================
__global__ void __launch_bounds__(256)
convert_stat_k(const float* __restrict__ x,
               __nv_bfloat162* __restrict__ hi, __nv_bfloat162* __restrict__ lo)
{
    size_t i = (size_t)blockIdx.x * 256 + threadIdx.x;   // 8388608 quads
    float4 v = ((const float4*)x)[i];
    __nv_bfloat162 h0 = __floats2bfloat162_rn(v.x, v.y);
    __nv_bfloat162 h1 = __floats2bfloat162_rn(v.z, v.w);
    float r0 = v.x - __bfloat162float(h0.x);
    float r1 = v.y - __bfloat162float(h0.y);
    float r2 = v.z - __bfloat162float(h1.x);
    float r3 = v.w - __bfloat162float(h1.y);
    hi[2 * i] = h0; hi[2 * i + 1] = h1;
    lo[2 * i] = __floats2bfloat162_rn(r0, r1);
    lo[2 * i + 1] = __floats2bfloat162_rn(r2, r3);
}

// Bcat[1536][512]: rows 0-511 encW static, 512-1023 tgtW static, 1024-1535 ptrW static
__global__ void __launch_bounds__(256)
convert_w_k(const float* __restrict__ encW, const float* __restrict__ tgtW,
            const float* __restrict__ ptrW,
            __nv_bfloat162* __restrict__ hi, __nv_bfloat162* __restrict__ lo)
{
    int i = blockIdx.x * 256 + threadIdx.x;              // 196608 quads
    int e = i * 4;
    int row = e >> 9, k = e & 511;
    const float* src;
    if (row < 512)       src = encW + (size_t)row * 1024 + k;
    else if (row < 1024) src = tgtW + (size_t)(row - 512) * 1024 + k;
    else                 src = ptrW + (size_t)(row - 1024) * 1536 + k;
    float4 v = *(const float4*)src;
    __nv_bfloat162 h0 = __floats2bfloat162_rn(v.x, v.y);
    __nv_bfloat162 h1 = __floats2bfloat162_rn(v.z, v.w);
    float r0 = v.x - __bfloat162float(h0.x);
    float r1 = v.y - __bfloat162float(h0.y);
    float r2 = v.z - __bfloat162float(h1.x);
    float r3 = v.w - __bfloat162float(h1.y);
    hi[2 * i] = h0; hi[2 * i + 1] = h1;
    lo[2 * i] = __floats2bfloat162_rn(r0, r1);
    lo[2 * i + 1] = __floats2bfloat162_rn(r2, r3);
}

// ===========================================================================
// Small GEMM: C[128 x N] = A[128x512] @ W^T, W elem = W[c*ldw + wofs + k]
// tile 32 rows x 64 cols, 256 threads, grid (N/64, 4)
// ===========================================================================
__global__ void __launch_bounds__(256)
small_gemm_k(const float* __restrict__ A, const float* __restrict__ W,
             int ldw, int wofs, float* __restrict__ C, int ldc)
{
    __shared__ float As[32][33];
    __shared__ float Ws[64][33];
    int t = threadIdx.x;
    int c = t & 63, rg = t >> 6;
    int row0 = blockIdx.y * 32, col0 = blockIdx.x * 64;
    float acc[8];
#pragma unroll
    for (int i = 0; i < 8; i++) acc[i] = 0.f;

    for (int k0 = 0; k0 < 512; k0 += 32) {
        {
            int idx = t * 4, row = idx >> 5, kk = idx & 31;
            float4 v = *(const float4*)(A + (size_t)(row0 + row) * 512 + k0 + kk);
            As[row][kk] = v.x; As[row][kk + 1] = v.y;
            As[row][kk + 2] = v.z; As[row][kk + 3] = v.w;
        }
        {
            int idx = t * 8, row = idx >> 5, kk = idx & 31;
            const float* s = W + (size_t)(col0 + row) * ldw + wofs + k0 + kk;
            float4 v0 = *(const float4*)s;
            float4 v1 = *(const float4*)(s + 4);
            Ws[row][kk] = v0.x; Ws[row][kk + 1] = v0.y;
            Ws[row][kk + 2] = v0.z; Ws[row][kk + 3] = v0.w;
            Ws[row][kk + 4] = v1.x; Ws[row][kk + 5] = v1.y;
            Ws[row][kk + 6] = v1.z; Ws[row][kk + 7] = v1.w;
        }
        __syncthreads();
#pragma unroll
        for (int kk = 0; kk < 32; kk++) {
            float wv = Ws[c][kk];
#pragma unroll
            for (int i = 0; i < 8; i++)
                acc[i] += As[rg * 8 + i][kk] * wv;
        }
        __syncthreads();
    }
#pragma unroll
    for (int i = 0; i < 8; i++)
        C[(size_t)(row0 + rg * 8 + i) * ldc + col0 + c] = acc[i];
}

// ===========================================================================
__global__ void gru_gates_k(const float* __restrict__ gx, const float* __restrict__ gh,
                            const float* __restrict__ bih, const float* __restrict__ bhh,
                            const float* __restrict__ lhh,
                            float* __restrict__ hnew, float* __restrict__ outh)
{
    int i = blockIdx.x * blockDim.x + threadIdx.x;
    int b = i >> 9, j = i & 511;
    const float* gxb = gx + b * 1536;
    const float* ghb = gh + b * 1536;
    float xr = gxb[j] + bih[j],              hr = ghb[j] + bhh[j];
    float xz = gxb[512 + j] + bih[512 + j],  hz = ghb[512 + j] + bhh[512 + j];
    float xn = gxb[1024 + j] + bih[1024 + j];
    float hn = ghb[1024 + j] + bhh[1024 + j];
    float r = 1.f / (1.f + expf(-(xr + hr)));
    float z = 1.f / (1.f + expf(-(xz + hz)));
    float n = tanhf(xn + r * hn);
    float h = lhh[i];
    float v = (1.f - z) * n + z * h;
    hnew[i] = v;
    outh[i] = v;
}

// ===========================================================================
// Big fused tensor-core GEMM (mma.sync bf16, 3-term hi/lo split).
// grid (3, 512): g = {enc, tgt, ptr}, 128 rows per CTA, N=512 via 4 ht-tiles.
// Per K-chunk of 32 the products AhBh, AhBl, AlBh accumulate into one C.
// SMEM layout (dynamic):
//   [0, 81920): pipeline: 2 bufs x 4 tiles (AH, AL, BH, BL), tile = 128x40 bf16
//   overlay [0, 67584): transpose tile 128x132 f32 (ptr epilogue only)
//   [81920): DV 512f, [83968): VV 512f, [86016): RED 4x128 f
// ===========================================================================
#define TILE_B   10240          // 128 * 40 halves * 2B
#define BUF_B    40960          // 4 tiles
#define SM_DV    81920
#define SM_VV    83968
#define SM_RED   86016
#define SMEM_BIG 88064

__device__ __forceinline__ void load_stage(
    unsigned sbase, int bufbase, int kt, int t, int row0, int grow,
    const __nv_bfloat16* __restrict__ shi, const __nv_bfloat16* __restrict__ slo,
    const __nv_bfloat16* __restrict__ bhi, const __nv_bfloat16* __restrict__ blo)
{
    int tsel = t >> 6;           // 0:AH 1:AL 2:BH 3:BL
    int tt = t & 63;
    const __nv_bfloat16* base =
        (tsel == 0) ? shi : (tsel == 1) ? slo : (tsel == 2) ? bhi : blo;
    int roff = (tsel < 2) ? row0 : grow;
    unsigned stile = sbase + (unsigned)(bufbase + tsel * TILE_B);
#pragma unroll
    for (int c = 0; c < 8; c++) {
        int row = tt * 2 + (c & 1);
        int chunk = c >> 1;
        cp16(stile + (unsigned)(row * 80 + chunk * 16),
             base + (size_t)(roff + row) * 512 + kt * 32 + chunk * 8);
    }
}

__global__ void __launch_bounds__(256, 2)
big_mma_k(const __nv_bfloat16* __restrict__ shi, const __nv_bfloat16* __restrict__ slo,
          const __nv_bfloat16* __restrict__ bhi, const __nv_bfloat16* __restrict__ blo,
          const float* __restrict__ denc, const float* __restrict__ dtgt,
          const float* __restrict__ encv, const float* __restrict__ tgtv,
          float* __restrict__ sc_e, float* __restrict__ sc_t,
          float* __restrict__ SbigT)
{
    extern __shared__ __align__(128) unsigned char smem[];
    unsigned sbase = smem_u32(smem);
    int t = threadIdx.x;
    int lane = t & 31, wid = t >> 5;
    int wm = wid & 1, wn = wid >> 1;         // warp tile: rows wm*64, cols wn*32
    int qr = lane >> 2, qc = lane & 3;
    int g = blockIdx.x;
    int row0 = blockIdx.y * 128;
    int b = blockIdx.y >> 2;
    int grow = g * 512;                      // + ht*128 added per tile

    float* DV  = (float*)(smem + SM_DV);
    float* VV  = (float*)(smem + SM_VV);
    float* RED = (float*)(smem + SM_RED);
    if (g < 2) {
        const float* dsrc = g ? dtgt : denc;
        const float* vsrc = g ? tgtv : encv;
        for (int i = t; i < 512; i += 256) { DV[i] = dsrc[b * 512 + i]; VV[i] = vsrc[i]; }
    }

    float sacc[4][2];
#pragma unroll
    for (int i = 0; i < 4; i++) { sacc[i][0] = 0.f; sacc[i][1] = 0.f; }

    for (int ht = 0; ht < 4; ht++) {
        int gr = grow + ht * 128;
        float acc[4][4][4];
#pragma unroll
        for (int mi = 0; mi < 4; mi++)
#pragma unroll
            for (int nj = 0; nj < 4; nj++)
#pragma unroll
                for (int r = 0; r < 4; r++) acc[mi][nj][r] = 0.f;

        load_stage(sbase, 0, 0, t, row0, gr, shi, slo, bhi, blo);
        CP_COMMIT();

        for (int kt = 0; kt < 16; kt++) {
            int bufbase = (kt & 1) * BUF_B;
            if (kt < 15) {
                load_stage(sbase, (bufbase ^ BUF_B), kt + 1, t, row0, gr,
                           shi, slo, bhi, blo);
                CP_COMMIT();
                CP_WAIT1();
            } else {
                CP_WAIT0();
            }
            __syncthreads();

            const unsigned char* AH = smem + bufbase;
            const unsigned char* AL = AH + TILE_B;
            const unsigned char* BH = AH + 2 * TILE_B;
            const unsigned char* BL = AH + 3 * TILE_B;

#pragma unroll
            for (int k16 = 0; k16 < 2; k16++) {
                int kb = k16 * 32;           // byte offset within row
                unsigned a[4][4], bb[4][2];
                // ---- load AH frags ----
#pragma unroll
                for (int mi = 0; mi < 4; mi++) {
                    int r = wm * 64 + mi * 16 + qr;
                    const unsigned char* p = AH + r * 80 + kb + qc * 4;
                    a[mi][0] = *(const unsigned*)(p);
                    a[mi][1] = *(const unsigned*)(p + 8 * 80);
                    a[mi][2] = *(const unsigned*)(p + 16);
                    a[mi][3] = *(const unsigned*)(p + 8 * 80 + 16);
                }
                // ---- load BH frags ----
#pragma unroll
                for (int nj = 0; nj < 4; nj++) {
                    int cr = wn * 32 + nj * 8 + qr;
                    const unsigned char* p = BH + cr * 80 + kb + qc * 4;
                    bb[nj][0] = *(const unsigned*)(p);
                    bb[nj][1] = *(const unsigned*)(p + 16);
                }
                // ---- AH x BH ----
#pragma unroll
                for (int mi = 0; mi < 4; mi++)
#pragma unroll
                    for (int nj = 0; nj < 4; nj++)
                        mma16816(acc[mi][nj], a[mi][0], a[mi][1], a[mi][2], a[mi][3],
                                 bb[nj][0], bb[nj][1]);
                // ---- load BL frags, AH x BL ----
                {
                    unsigned bl[4][2];
#pragma unroll
                    for (int nj = 0; nj < 4; nj++) {
                        int cr = wn * 32 + nj * 8 + qr;
                        const unsigned char* p = BL + cr * 80 + kb + qc * 4;
                        bl[nj][0] = *(const unsigned*)(p);
                        bl[nj][1] = *(const unsigned*)(p + 16);
                    }
#pragma unroll
                    for (int mi = 0; mi < 4; mi++)
#pragma unroll
                        for (int nj = 0; nj < 4; nj++)
                            mma16816(acc[mi][nj], a[mi][0], a[mi][1], a[mi][2], a[mi][3],
                                     bl[nj][0], bl[nj][1]);
                }
                // ---- load AL frags (overwrite a), AL x BH ----
#pragma unroll
                for (int mi = 0; mi < 4; mi++) {
                    int r = wm * 64 + mi * 16 + qr;
                    const unsigned char* p = AL + r * 80 + kb + qc * 4;
                    a[mi][0] = *(const unsigned*)(p);
                    a[mi][1] = *(const unsigned*)(p + 8 * 80);
                    a[mi][2] = *(const unsigned*)(p + 16);
                    a[mi][3] = *(const unsigned*)(p + 8 * 80 + 16);
                }
#pragma unroll
                for (int mi = 0; mi < 4; mi++)
#pragma unroll
                    for (int nj = 0; nj < 4; nj++)
                        mma16816(acc[mi][nj], a[mi][0], a[mi][1], a[mi][2], a[mi][3],
                                 bb[nj][0], bb[nj][1]);
            }
            __syncthreads();
        }

        // ---------------- per-ht epilogue ----------------
        if (g < 2) {
#pragma unroll
            for (int mi = 0; mi < 4; mi++)
#pragma unroll
                for (int nj = 0; nj < 4; nj++) {
                    int c0 = ht * 128 + wn * 32 + nj * 8 + qc * 2;
                    float d0 = DV[c0], d1 = DV[c0 + 1];
                    float v0 = VV[c0], v1 = VV[c0 + 1];
                    sacc[mi][0] += v0 * tanhf(acc[mi][nj][0] + d0)
                                 + v1 * tanhf(acc[mi][nj][1] + d1);
                    sacc[mi][1] += v0 * tanhf(acc[mi][nj][2] + d0)
                                 + v1 * tanhf(acc[mi][nj][3] + d1);
                }
        } else {
            float* T = (float*)smem;         // overlay (post-sync, pre-next-prologue)
#pragma unroll
            for (int mi = 0; mi < 4; mi++)
#pragma unroll
                for (int nj = 0; nj < 4; nj++) {
                    int cl = wn * 32 + nj * 8 + qc * 2;
                    int rl = wm * 64 + mi * 16 + qr;
                    T[cl * 132 + rl]           = acc[mi][nj][0];
                    T[(cl + 1) * 132 + rl]     = acc[mi][nj][1];
                    T[cl * 132 + rl + 8]       = acc[mi][nj][2];
                    T[(cl + 1) * 132 + rl + 8] = acc[mi][nj][3];
                }
            __syncthreads();
#pragma unroll 1
            for (int c = wid * 16; c < wid * 16 + 16; c++) {
                float4 v = *(const float4*)(T + c * 132 + lane * 4);
                *(float4*)(SbigT + (size_t)(ht * 128 + c) * 65536 + row0 + lane * 4) = v;
            }
            __syncthreads();
        }
    }

    if (g < 2) {
        // reduce over the 4 lanes sharing a row (qc), then across n-warps via smem
#pragma unroll
        for (int mi = 0; mi < 4; mi++) {
#pragma unroll
            for (int h = 0; h < 2; h++) {
                float s = sacc[mi][h];
                s += __shfl_xor_sync(0xffffffffu, s, 1);
                s += __shfl_xor_sync(0xffffffffu, s, 2);
                sacc[mi][h] = s;
            }
        }
        if (qc == 0) {
#pragma unroll
            for (int mi = 0; mi < 4; mi++) {
                int r = wm * 64 + mi * 16 + qr;
                RED[wn * 128 + r]     = sacc[mi][0];
                RED[wn * 128 + r + 8] = sacc[mi][1];
            }
        }
        __syncthreads();
        if (t < 128) {
            float s = RED[t] + RED[128 + t] + RED[256 + t] + RED[384 + t];
            (g ? sc_t : sc_e)[row0 + t] = s;
        }
    }
}

// ===========================================================================
__global__ void softmax_k(const float* __restrict__ score_e, const float* __restrict__ score_t,
                          float* __restrict__ attn_e, float* __restrict__ attn_t)
{
    int b = blockIdx.x & 127;
    int wh = blockIdx.x >> 7;
    const float* src = (wh ? score_t : score_e) + b * 512;
    float* dst = (wh ? attn_t : attn_e) + b * 512;
    int t = threadIdx.x;
    float v0 = src[t], v1 = src[t + 256];
    __shared__ float red[256];
    red[t] = fmaxf(v0, v1);
    __syncthreads();
    for (int s = 128; s > 0; s >>= 1) {
        if (t < s) red[t] = fmaxf(red[t], red[t + s]);
        __syncthreads();
    }
    float mx = red[0];
    __syncthreads();
    float e0 = expf(v0 - mx), e1 = expf(v1 - mx);
    red[t] = e0 + e1;
    __syncthreads();
    for (int s = 128; s > 0; s >>= 1) {
        if (t < s) red[t] += red[t + s];
        __syncthreads();
    }
    float inv = 1.f / red[0];
    dst[t] = e0 * inv;
    dst[t + 256] = e1 * inv;
}

__global__ void context_k(const float* __restrict__ stat,
                          const float* __restrict__ ae, const float* __restrict__ at,
                          float* __restrict__ ce, float* __restrict__ ct)
{
    int b = blockIdx.x >> 2;
    int ch = blockIdx.x & 3;
    int h = ch * 128 + threadIdx.x;
    __shared__ float sae[512], sat[512];
    for (int i = threadIdx.x; i < 512; i += 128) {
        sae[i] = ae[b * 512 + i];
        sat[i] = at[b * 512 + i];
    }
    __syncthreads();
    const float* Sb = stat + (size_t)b * 262144 + h;
    float se = 0.f, st = 0.f;
#pragma unroll 8
    for (int n = 0; n < 512; n++) {
        float sv = Sb[(size_t)n * 512];
        se += sae[n] * sv;
        st += sat[n] * sv;
    }
    ce[b * 512 + h] = se;
    ct[b * 512 + h] = st;
}

// Final pointer scores from transposed S: fully coalesced reads.
__global__ void __launch_bounds__(256)
final_k(const float* __restrict__ SbigT,
        const float* __restrict__ cp, const float* __restrict__ ctp,
        const float* __restrict__ ss, const float* __restrict__ vp,
        float* __restrict__ out)
{
    __shared__ float a1[512], a2[512], vv[512];
    int b = blockIdx.x >> 1;                 // 256 blocks, 2 per batch
    int t = threadIdx.x;
    for (int i = t; i < 512; i += 256) {
        float s0 = ss[b * 512 + i];
        a1[i] = cp[b * 512 + i] + s0;
        a2[i] = ctp[b * 512 + i] + s0;
        vv[i] = vp[i];
    }
    __syncthreads();
    int row = blockIdx.x * 256 + t;
    float s1 = 0.f, s2 = 0.f;
#pragma unroll 4
    for (int h = 0; h < 512; h++) {
        float x = __ldg(SbigT + (size_t)h * 65536 + row);
        float v = vv[h];
        s1 += v * tanhf(x + a1[h]);
        s2 += v * tanhf(x + a2[h]);
    }
    out[row] = 5.0f * s1 + s2;
}

// ===========================================================================
extern "C" void kernel_launch(void* const* d_in, const int* in_sizes, int n_in,
                              void* d_out, int out_size)
{
    const float* stat = (const float*)d_in[0];   // (128,512,512)
    const float* semb = (const float*)d_in[1];   // (128,1,512)
    const float* dech = (const float*)d_in[2];   // (128,1,512)
    const float* tgth = (const float*)d_in[3];   // (128,1,512)
    const float* lhh  = (const float*)d_in[4];   // (1,128,512)
    const float* ptrv = (const float*)d_in[5];   // (1,1,512)
    const float* ptrW = (const float*)d_in[6];   // (1,512,1536)
    const float* encv = (const float*)d_in[7];   // (1,1,512)
    const float* encW = (const float*)d_in[8];   // (1,512,1024)
    const float* tgtv = (const float*)d_in[9];   // (1,1,512)
    const float* tgtW = (const float*)d_in[10];  // (1,512,1024)
    const float* wih  = (const float*)d_in[11];  // (1536,512)
    const float* whh  = (const float*)d_in[12];  // (1536,512)
    const float* bih  = (const float*)d_in[13];
    const float* bhh  = (const float*)d_in[14];
    float* out = (float*)d_out;

    unsigned char* base = nullptr;
    cudaGetSymbolAddress((void**)&base, g_scratch);
    float* SbigT = (float*)(base + OFF_SBIGT);
    __nv_bfloat16* shi = (__nv_bfloat16*)(base + OFF_SHI);
    __nv_bfloat16* slo = (__nv_bfloat16*)(base + OFF_SLO);
    __nv_bfloat16* bhi = (__nv_bfloat16*)(base + OFF_BHI);
    __nv_bfloat16* blo = (__nv_bfloat16*)(base + OFF_BLO);
    float* FL = (float*)(base + OFF_FL);
    float* gx     = FL + FO_GX;
    float* gh     = FL + FO_GH;
    float* hnew   = FL + FO_HNEW;
    float* denc   = FL + FO_DENC;
    float* dtgt   = FL + FO_DTGT;
    float* sstate = FL + FO_SSTATE;
    float* cptr   = FL + FO_CPTR;
    float* ctptr  = FL + FO_CTPTR;
    float* ctxe   = FL + FO_CTXE;
    float* ctxt   = FL + FO_CTXT;
    float* sc_e   = FL + FO_SCE;
    float* sc_t   = FL + FO_SCT;
    float* at_e   = FL + FO_ATE;
    float* at_t   = FL + FO_ATT;

    // Attribute cache: set once on the (uncaptured) correctness call; avoids
    // non-stream API calls during graph capture. (Same pattern passed in R4.)
    static bool attr_done = false;
    if (!attr_done) {
        cudaFuncSetAttribute(big_mma_k, cudaFuncAttributeMaxDynamicSharedMemorySize,
                             SMEM_BIG);
        attr_done = true;
    }

    // conversions
    convert_stat_k<<<32768, 256>>>(stat, (__nv_bfloat162*)shi, (__nv_bfloat162*)slo);
    convert_w_k<<<768, 256>>>(encW, tgtW, ptrW, (__nv_bfloat162*)bhi, (__nv_bfloat162*)blo);

    // GRU
    small_gemm_k<<<dim3(24, 4), 256>>>(dech, wih, 512, 0, gx, 1536);
    small_gemm_k<<<dim3(24, 4), 256>>>(lhh,  whh, 512, 0, gh, 1536);
    gru_gates_k<<<256, 256>>>(gx, gh, bih, bhh, lhh, hnew, out + 65536);

    // per-batch bias projections
    small_gemm_k<<<dim3(8, 4), 256>>>(hnew, encW, 1024, 512,  denc,   512);
    small_gemm_k<<<dim3(8, 4), 256>>>(tgth, tgtW, 1024, 512,  dtgt,   512);
    small_gemm_k<<<dim3(8, 4), 256>>>(semb, ptrW, 1536, 1024, sstate, 512);

    // big tensor-core GEMM: enc scores, tgt scores, S_ptr (transposed)
    big_mma_k<<<dim3(3, 512), 256, SMEM_BIG>>>(shi, slo, bhi, blo, denc, dtgt,
                                               encv, tgtv, sc_e, sc_t, SbigT);

    // softmax + contexts + context projections
    softmax_k<<<256, 256>>>(sc_e, sc_t, at_e, at_t);
    context_k<<<512, 128>>>(stat, at_e, at_t, ctxe, ctxt);
    small_gemm_k<<<dim3(8, 4), 256>>>(ctxe, ptrW, 1536, 512, cptr,  512);
    small_gemm_k<<<dim3(8, 4), 256>>>(ctxt, ptrW, 1536, 512, ctptr, 512);

    // final pointer scores
    final_k<<<256, 256>>>(SbigT, cptr, ctptr, sstate, ptrv, out);
}

// round 9
// speedup vs baseline: 1.8762x; 1.0841x over previous
#include <cuda_runtime.h>
#include <cuda_bf16.h>

// ===========================================================================
// B=128, N=512, H=512.  Output: [probs 65536 | new_last_hh 65536] fp32
// Big GEMM on tensor cores via mma.sync bf16 + ldmatrix (sm_103-safe).
// ===========================================================================

// -------------------- scratch (byte offsets) --------------------------------
#define OFF_SBIGT  0L                       // 512*65536 f32 (S_ptr, [h][row])
#define OFF_SHI    134217728L               // stat hi bf16 [65536][512]
#define OFF_SLO    201326592L               // stat lo bf16
#define OFF_BHI    268435456L               // Bcat hi bf16 [1536][512]
#define OFF_BLO    270008320L
#define OFF_FL     271581184L               // float region
#define SCRATCH_BYTES (OFF_FL + 4718592L)
__device__ __align__(1024) unsigned char g_scratch[SCRATCH_BYTES];

// float sub-offsets (in floats) inside FL region
#define FO_GX     0L
#define FO_GH     196608L
#define FO_HNEW   393216L
#define FO_DENC   458752L
#define FO_DTGT   524288L
#define FO_SSTATE 589824L
#define FO_CPTR   655360L
#define FO_CTPTR  720896L
#define FO_CTXE   786432L
#define FO_CTXT   851968L
#define FO_SCE    917504L
#define FO_SCT    983040L
#define FO_ATE    1048576L
#define FO_ATT    1114112L

// ===================== PTX helpers (baseline ISA only) ======================
__device__ __forceinline__ unsigned smem_u32(const void* p) {
    unsigned a;
    asm("{ .reg .u64 t; cvta.to.shared.u64 t, %1; cvt.u32.u64 %0, t; }"
        : "=r"(a) : "l"(p));
    return a;
}
__device__ __forceinline__ void cp16(unsigned dst, const void* src) {
    asm volatile("cp.async.cg.shared.global [%0], [%1], 16;" :: "r"(dst), "l"(src));
}
#define CP_COMMIT() asm volatile("cp.async.commit_group;" ::: "memory")
#define CP_WAIT1()  asm volatile("cp.async.wait_group 1;" ::: "memory")
#define CP_WAIT0()  asm volatile("cp.async.wait_group 0;" ::: "memory")

__device__ __forceinline__ void mma16816(float c[4],
        unsigned a0, unsigned a1, unsigned a2, unsigned a3,
        unsigned b0, unsigned b1) {
    asm volatile(
        "mma.sync.aligned.m16n8k16.row.col.f32.bf16.bf16.f32 "
        "{%0,%1,%2,%3}, {%4,%5,%6,%7}, {%8,%9}, {%0,%1,%2,%3};"
        : "+f"(c[0]), "+f"(c[1]), "+f"(c[2]), "+f"(c[3])
        : "r"(a0), "r"(a1), "r"(a2), "r"(a3), "r"(b0), "r"(b1));
}
__device__ __forceinline__ void ldsm4(unsigned r[4], unsigned addr) {
    asm volatile("ldmatrix.sync.aligned.m8n8.x4.shared.b16 {%0,%1,%2,%3}, [%4];"
        : "=r"(r[0]), "=r"(r[1]), "=r"(r[2]), "=r"(r[3]) : "r"(addr));
}

// ===========================================================================
// fp32 -> (bf16 hi, bf16 lo) conversions
// ===========================================================================
__global__ void __launch_bounds__(256)
convert_stat_k(const float* __restrict__ x,
               __nv_bfloat162* __restrict__ hi, __nv_bfloat162* __restrict__ lo)
{
    size_t i = (size_t)blockIdx.x * 256 + threadIdx.x;   // 8388608 quads
    float4 v = ((const float4*)x)[i];
    __nv_bfloat162 h0 = __floats2bfloat162_rn(v.x, v.y);
    __nv_bfloat162 h1 = __floats2bfloat162_rn(v.z, v.w);
    float r0 = v.x - __bfloat162float(h0.x);
    float r1 = v.y - __bfloat162float(h0.y);
    float r2 = v.z - __bfloat162float(h1.x);
    float r3 = v.w - __bfloat162float(h1.y);
    hi[2 * i] = h0; hi[2 * i + 1] = h1;
    lo[2 * i] = __floats2bfloat162_rn(r0, r1);
    lo[2 * i + 1] = __floats2bfloat162_rn(r2, r3);
}

// Bcat[1536][512]: rows 0-511 encW static, 512-1023 tgtW static, 1024-1535 ptrW static
__global__ void __launch_bounds__(256)
convert_w_k(const float* __restrict__ encW, const float* __restrict__ tgtW,
            const float* __restrict__ ptrW,
            __nv_bfloat162* __restrict__ hi, __nv_bfloat162* __restrict__ lo)
{
    int i = blockIdx.x * 256 + threadIdx.x;              // 196608 quads
    int e = i * 4;
    int row = e >> 9, k = e & 511;
    const float* src;
    if (row < 512)       src = encW + (size_t)row * 1024 + k;
    else if (row < 1024) src = tgtW + (size_t)(row - 512) * 1024 + k;
    else                 src = ptrW + (size_t)(row - 1024) * 1536 + k;
    float4 v = *(const float4*)src;
    __nv_bfloat162 h0 = __floats2bfloat162_rn(v.x, v.y);
    __nv_bfloat162 h1 = __floats2bfloat162_rn(v.z, v.w);
    float r0 = v.x - __bfloat162float(h0.x);
    float r1 = v.y - __bfloat162float(h0.y);
    float r2 = v.z - __bfloat162float(h1.x);
    float r3 = v.w - __bfloat162float(h1.y);
    hi[2 * i] = h0; hi[2 * i + 1] = h1;
    lo[2 * i] = __floats2bfloat162_rn(r0, r1);
    lo[2 * i + 1] = __floats2bfloat162_rn(r2, r3);
}

// ===========================================================================
// Small GEMM, z-batched: up to 3 independent C[128 x N] = A[128x512] @ W^T
// tile 32 rows x 64 cols, 256 threads, grid (N/64, 4, nz)
// ===========================================================================
__global__ void __launch_bounds__(256)
small_gemm3_k(const float* A0, const float* W0, int ldw0, int wofs0, float* C0, int ldc0,
              const float* A1, const float* W1, int ldw1, int wofs1, float* C1, int ldc1,
              const float* A2, const float* W2, int ldw2, int wofs2, float* C2, int ldc2)
{
    int z = blockIdx.z;
    const float* A = (z == 0) ? A0 : (z == 1) ? A1 : A2;
    const float* W = (z == 0) ? W0 : (z == 1) ? W1 : W2;
    int ldw  = (z == 0) ? ldw0  : (z == 1) ? ldw1  : ldw2;
    int wofs = (z == 0) ? wofs0 : (z == 1) ? wofs1 : wofs2;
    float* C = (z == 0) ? C0 : (z == 1) ? C1 : C2;
    int ldc  = (z == 0) ? ldc0 : (z == 1) ? ldc1 : ldc2;

    __shared__ float As[32][33];
    __shared__ float Ws[64][33];
    int t = threadIdx.x;
    int c = t & 63, rg = t >> 6;
    int row0 = blockIdx.y * 32, col0 = blockIdx.x * 64;
    float acc[8];
#pragma unroll
    for (int i = 0; i < 8; i++) acc[i] = 0.f;

    for (int k0 = 0; k0 < 512; k0 += 32) {
        {
            int idx = t * 4, row = idx >> 5, kk = idx & 31;
            float4 v = *(const float4*)(A + (size_t)(row0 + row) * 512 + k0 + kk);
            As[row][kk] = v.x; As[row][kk + 1] = v.y;
            As[row][kk + 2] = v.z; As[row][kk + 3] = v.w;
        }
        {
            int idx = t * 8, row = idx >> 5, kk = idx & 31;
            const float* s = W + (size_t)(col0 + row) * ldw + wofs + k0 + kk;
            float4 v0 = *(const float4*)s;
            float4 v1 = *(const float4*)(s + 4);
            Ws[row][kk] = v0.x; Ws[row][kk + 1] = v0.y;
            Ws[row][kk + 2] = v0.z; Ws[row][kk + 3] = v0.w;
            Ws[row][kk + 4] = v1.x; Ws[row][kk + 5] = v1.y;
            Ws[row][kk + 6] = v1.z; Ws[row][kk + 7] = v1.w;
        }
        __syncthreads();
#pragma unroll
        for (int kk = 0; kk < 32; kk++) {
            float wv = Ws[c][kk];
#pragma unroll
            for (int i = 0; i < 8; i++)
                acc[i] += As[rg * 8 + i][kk] * wv;
        }
        __syncthreads();
    }
#pragma unroll
    for (int i = 0; i < 8; i++)
        C[(size_t)(row0 + rg * 8 + i) * ldc + col0 + c] = acc[i];
}

// ===========================================================================
__global__ void gru_gates_k(const float* __restrict__ gx, const float* __restrict__ gh,
                            const float* __restrict__ bih, const float* __restrict__ bhh,
                            const float* __restrict__ lhh,
                            float* __restrict__ hnew, float* __restrict__ outh)
{
    int i = blockIdx.x * blockDim.x + threadIdx.x;
    int b = i >> 9, j = i & 511;
    const float* gxb = gx + b * 1536;
    const float* ghb = gh + b * 1536;
    float xr = gxb[j] + bih[j],              hr = ghb[j] + bhh[j];
    float xz = gxb[512 + j] + bih[512 + j],  hz = ghb[512 + j] + bhh[512 + j];
    float xn = gxb[1024 + j] + bih[1024 + j];
    float hn = ghb[1024 + j] + bhh[1024 + j];
    float r = 1.f / (1.f + expf(-(xr + hr)));
    float z = 1.f / (1.f + expf(-(xz + hz)));
    float n = tanhf(xn + r * hn);
    float h = lhh[i];
    float v = (1.f - z) * n + z * h;
    hnew[i] = v;
    outh[i] = v;
}

// ===========================================================================
// Big fused tensor-core GEMM (mma.sync bf16 + ldmatrix, 3-term hi/lo split).
// grid (3, 512): g = {enc, tgt, ptr}, 128 rows per CTA, N=512 via 4 ht-tiles.
// Product order per k16: AH*BH -> AL*BH -> AH*BL (one B-frag set live).
// SMEM: [0,81920) 2 bufs x 4 tiles (AH,AL,BH,BL), tile = 128 rows x 80B
//       overlay [0,67584): transpose tile 128x132 f32 (ptr epilogue)
//       [81920) DV 512f, [83968) VV 512f, [86016) RED 4x128 f
// ===========================================================================
#define TILE_B   10240
#define BUF_B    40960
#define SM_DV    81920
#define SM_VV    83968
#define SM_RED   86016
#define SMEM_BIG 88064

__device__ __forceinline__ void load_stage(
    unsigned sbase, int bufbase, int kt, int t, int row0, int grow,
    const __nv_bfloat16* __restrict__ shi, const __nv_bfloat16* __restrict__ slo,
    const __nv_bfloat16* __restrict__ bhi, const __nv_bfloat16* __restrict__ blo)
{
    int tsel = t >> 6;           // 0:AH 1:AL 2:BH 3:BL
    int tt = t & 63;
    const __nv_bfloat16* base =
        (tsel == 0) ? shi : (tsel == 1) ? slo : (tsel == 2) ? bhi : blo;
    int roff = (tsel < 2) ? row0 : grow;
    unsigned stile = sbase + (unsigned)(bufbase + tsel * TILE_B);
#pragma unroll
    for (int c = 0; c < 8; c++) {
        int row = tt * 2 + (c & 1);
        int chunk = c >> 1;
        cp16(stile + (unsigned)(row * 80 + chunk * 16),
             base + (size_t)(roff + row) * 512 + kt * 32 + chunk * 8);
    }
}

__global__ void __launch_bounds__(256, 2)
big_mma_k(const __nv_bfloat16* __restrict__ shi, const __nv_bfloat16* __restrict__ slo,
          const __nv_bfloat16* __restrict__ bhi, const __nv_bfloat16* __restrict__ blo,
          const float* __restrict__ denc, const float* __restrict__ dtgt,
          const float* __restrict__ encv, const float* __restrict__ tgtv,
          float* __restrict__ sc_e, float* __restrict__ sc_t,
          float* __restrict__ SbigT)
{
    extern __shared__ __align__(128) unsigned char smem[];
    unsigned sbase = smem_u32(smem);
    int t = threadIdx.x;
    int lane = t & 31, wid = t >> 5;
    int wm = wid & 1, wn = wid >> 1;         // warp tile: rows wm*64, cols wn*32
    int qr = lane >> 2, qc = lane & 3;
    int g = blockIdx.x;
    int row0 = blockIdx.y * 128;
    int b = blockIdx.y >> 2;
    int grow = g * 512;

    // ldmatrix lane address components
    int lrow = lane & 7, lsel = lane >> 3;
    unsigned a_off = (unsigned)((wm * 64 + (lsel & 1) * 8 + lrow) * 80 + (lsel >> 1) * 16);
    unsigned b_off = (unsigned)((wn * 32 + (lsel >> 1) * 8 + lrow) * 80 + (lsel & 1) * 16);

    float* DV  = (float*)(smem + SM_DV);
    float* VV  = (float*)(smem + SM_VV);
    float* RED = (float*)(smem + SM_RED);
    if (g < 2) {
        const float* dsrc = g ? dtgt : denc;
        const float* vsrc = g ? tgtv : encv;
        for (int i = t; i < 512; i += 256) { DV[i] = dsrc[b * 512 + i]; VV[i] = vsrc[i]; }
    }

    float sacc[4][2];
#pragma unroll
    for (int i = 0; i < 4; i++) { sacc[i][0] = 0.f; sacc[i][1] = 0.f; }

    for (int ht = 0; ht < 4; ht++) {
        int gr = grow + ht * 128;
        float acc[4][4][4];
#pragma unroll
        for (int mi = 0; mi < 4; mi++)
#pragma unroll
            for (int nj = 0; nj < 4; nj++)
#pragma unroll
                for (int r = 0; r < 4; r++) acc[mi][nj][r] = 0.f;

        load_stage(sbase, 0, 0, t, row0, gr, shi, slo, bhi, blo);
        CP_COMMIT();

        for (int kt = 0; kt < 16; kt++) {
            int bufbase = (kt & 1) * BUF_B;
            if (kt < 15) {
                load_stage(sbase, (bufbase ^ BUF_B), kt + 1, t, row0, gr,
                           shi, slo, bhi, blo);
                CP_COMMIT();
                CP_WAIT1();
            } else {
                CP_WAIT0();
            }
            __syncthreads();

            unsigned AH = sbase + (unsigned)bufbase;
            unsigned AL = AH + TILE_B;
            unsigned BH = AH + 2 * TILE_B;
            unsigned BL = AH + 3 * TILE_B;

#pragma unroll
            for (int k16 = 0; k16 < 2; k16++) {
                unsigned kb = (unsigned)(k16 * 32);
                unsigned a[4][4], bb[2][4];
                // ---- AH x BH ----
#pragma unroll
                for (int mi = 0; mi < 4; mi++)
                    ldsm4(a[mi], AH + a_off + mi * 1280 + kb);
#pragma unroll
                for (int np = 0; np < 2; np++)
                    ldsm4(bb[np], BH + b_off + np * 1280 + kb);
#pragma unroll
                for (int mi = 0; mi < 4; mi++)
#pragma unroll
                    for (int nj = 0; nj < 4; nj++)
                        mma16816(acc[mi][nj], a[mi][0], a[mi][1], a[mi][2], a[mi][3],
                                 bb[nj >> 1][(nj & 1) * 2], bb[nj >> 1][(nj & 1) * 2 + 1]);
                // ---- AL x BH ----
#pragma unroll
                for (int mi = 0; mi < 4; mi++)
                    ldsm4(a[mi], AL + a_off + mi * 1280 + kb);
#pragma unroll
                for (int mi = 0; mi < 4; mi++)
#pragma unroll
                    for (int nj = 0; nj < 4; nj++)
                        mma16816(acc[mi][nj], a[mi][0], a[mi][1], a[mi][2], a[mi][3],
                                 bb[nj >> 1][(nj & 1) * 2], bb[nj >> 1][(nj & 1) * 2 + 1]);
                // ---- AH x BL ----
#pragma unroll
                for (int mi = 0; mi < 4; mi++)
                    ldsm4(a[mi], AH + a_off + mi * 1280 + kb);
#pragma unroll
                for (int np = 0; np < 2; np++)
                    ldsm4(bb[np], BL + b_off + np * 1280 + kb);
#pragma unroll
                for (int mi = 0; mi < 4; mi++)
#pragma unroll
                    for (int nj = 0; nj < 4; nj++)
                        mma16816(acc[mi][nj], a[mi][0], a[mi][1], a[mi][2], a[mi][3],
                                 bb[nj >> 1][(nj & 1) * 2], bb[nj >> 1][(nj & 1) * 2 + 1]);
            }
            __syncthreads();
        }

        // ---------------- per-ht epilogue ----------------
        if (g < 2) {
#pragma unroll
            for (int mi = 0; mi < 4; mi++)
#pragma unroll
                for (int nj = 0; nj < 4; nj++) {
                    int c0 = ht * 128 + wn * 32 + nj * 8 + qc * 2;
                    float d0 = DV[c0], d1 = DV[c0 + 1];
                    float v0 = VV[c0], v1 = VV[c0 + 1];
                    sacc[mi][0] += v0 * tanhf(acc[mi][nj][0] + d0)
                                 + v1 * tanhf(acc[mi][nj][1] + d1);
                    sacc[mi][1] += v0 * tanhf(acc[mi][nj][2] + d0)
                                 + v1 * tanhf(acc[mi][nj][3] + d1);
                }
        } else {
            float* T = (float*)smem;         // overlay (post-sync, pre-next-prologue)
#pragma unroll
            for (int mi = 0; mi < 4; mi++)
#pragma unroll
                for (int nj = 0; nj < 4; nj++) {
                    int cl = wn * 32 + nj * 8 + qc * 2;
                    int rl = wm * 64 + mi * 16 + qr;
                    T[cl * 132 + rl]           = acc[mi][nj][0];
                    T[(cl + 1) * 132 + rl]     = acc[mi][nj][1];
                    T[cl * 132 + rl + 8]       = acc[mi][nj][2];
                    T[(cl + 1) * 132 + rl + 8] = acc[mi][nj][3];
                }
            __syncthreads();
#pragma unroll 1
            for (int c = wid * 16; c < wid * 16 + 16; c++) {
                float4 v = *(const float4*)(T + c * 132 + lane * 4);
                *(float4*)(SbigT + (size_t)(ht * 128 + c) * 65536 + row0 + lane * 4) = v;
            }
            __syncthreads();
        }
    }

    if (g < 2) {
#pragma unroll
        for (int mi = 0; mi < 4; mi++) {
#pragma unroll
            for (int h = 0; h < 2; h++) {
                float s = sacc[mi][h];
                s += __shfl_xor_sync(0xffffffffu, s, 1);
                s += __shfl_xor_sync(0xffffffffu, s, 2);
                sacc[mi][h] = s;
            }
        }
        if (qc == 0) {
#pragma unroll
            for (int mi = 0; mi < 4; mi++) {
                int r = wm * 64 + mi * 16 + qr;
                RED[wn * 128 + r]     = sacc[mi][0];
                RED[wn * 128 + r + 8] = sacc[mi][1];
            }
        }
        __syncthreads();
        if (t < 128) {
            float s = RED[t] + RED[128 + t] + RED[256 + t] + RED[384 + t];
            (g ? sc_t : sc_e)[row0 + t] = s;
        }
    }
}

// ===========================================================================
__global__ void softmax_k(const float* __restrict__ score_e, const float* __restrict__ score_t,
                          float* __restrict__ attn_e, float* __restrict__ attn_t)
{
    int b = blockIdx.x & 127;
    int wh = blockIdx.x >> 7;
    const float* src = (wh ? score_t : score_e) + b * 512;
    float* dst = (wh ? attn_t : attn_e) + b * 512;
    int t = threadIdx.x;
    float v0 = src[t], v1 = src[t + 256];
    __shared__ float red[256];
    red[t] = fmaxf(v0, v1);
    __syncthreads();
    for (int s = 128; s > 0; s >>= 1) {
        if (t < s) red[t] = fmaxf(red[t], red[t + s]);
        __syncthreads();
    }
    float mx = red[0];
    __syncthreads();
    float e0 = expf(v0 - mx), e1 = expf(v1 - mx);
    red[t] = e0 + e1;
    __syncthreads();
    for (int s = 128; s > 0; s >>= 1) {
        if (t < s) red[t] += red[t + s];
        __syncthreads();
    }
    float inv = 1.f / red[0];
    dst[t] = e0 * inv;
    dst[t + 256] = e1 * inv;
}

__global__ void context_k(const float* __restrict__ stat,
                          const float* __restrict__ ae, const float* __restrict__ at,
                          float* __restrict__ ce, float* __restrict__ ct)
{
    int b = blockIdx.x >> 2;
    int ch = blockIdx.x & 3;
    int h = ch * 128 + threadIdx.x;
    __shared__ float sae[512], sat[512];
    for (int i = threadIdx.x; i < 512; i += 128) {
        sae[i] = ae[b * 512 + i];
        sat[i] = at[b * 512 + i];
    }
    __syncthreads();
    const float* Sb = stat + (size_t)b * 262144 + h;
    float se = 0.f, st = 0.f;
#pragma unroll 8
    for (int n = 0; n < 512; n++) {
        float sv = Sb[(size_t)n * 512];
        se += sae[n] * sv;
        st += sat[n] * sv;
    }
    ce[b * 512 + h] = se;
    ct[b * 512 + h] = st;
}

// Final pointer scores from transposed S: fully coalesced reads.
__global__ void __launch_bounds__(256)
final_k(const float* __restrict__ SbigT,
        const float* __restrict__ cp, const float* __restrict__ ctp,
        const float* __restrict__ ss, const float* __restrict__ vp,
        float* __restrict__ out)
{
    __shared__ float a1[512], a2[512], vv[512];
    int b = blockIdx.x >> 1;                 // 256 blocks, 2 per batch
    int t = threadIdx.x;
    for (int i = t; i < 512; i += 256) {
        float s0 = ss[b * 512 + i];
        a1[i] = cp[b * 512 + i] + s0;
        a2[i] = ctp[b * 512 + i] + s0;
        vv[i] = vp[i];
    }
    __syncthreads();
    int row = blockIdx.x * 256 + t;
    float s1 = 0.f, s2 = 0.f;
#pragma unroll 4
    for (int h = 0; h < 512; h++) {
        float x = __ldg(SbigT + (size_t)h * 65536 + row);
        float v = vv[h];
        s1 += v * tanhf(x + a1[h]);
        s2 += v * tanhf(x + a2[h]);
    }
    out[row] = 5.0f * s1 + s2;
}

// ===========================================================================
extern "C" void kernel_launch(void* const* d_in, const int* in_sizes, int n_in,
                              void* d_out, int out_size)
{
    const float* stat = (const float*)d_in[0];   // (128,512,512)
    const float* semb = (const float*)d_in[1];   // (128,1,512)
    const float* dech = (const float*)d_in[2];   // (128,1,512)
    const float* tgth = (const float*)d_in[3];   // (128,1,512)
    const float* lhh  = (const float*)d_in[4];   // (1,128,512)
    const float* ptrv = (const float*)d_in[5];   // (1,1,512)
    const float* ptrW = (const float*)d_in[6];   // (1,512,1536)
    const float* encv = (const float*)d_in[7];   // (1,1,512)
    const float* encW = (const float*)d_in[8];   // (1,512,1024)
    const float* tgtv = (const float*)d_in[9];   // (1,1,512)
    const float* tgtW = (const float*)d_in[10];  // (1,512,1024)
    const float* wih  = (const float*)d_in[11];  // (1536,512)
    const float* whh  = (const float*)d_in[12];  // (1536,512)
    const float* bih  = (const float*)d_in[13];
    const float* bhh  = (const float*)d_in[14];
    float* out = (float*)d_out;

    unsigned char* base = nullptr;
    cudaGetSymbolAddress((void**)&base, g_scratch);
    float* SbigT = (float*)(base + OFF_SBIGT);
    __nv_bfloat16* shi = (__nv_bfloat16*)(base + OFF_SHI);
    __nv_bfloat16* slo = (__nv_bfloat16*)(base + OFF_SLO);
    __nv_bfloat16* bhi = (__nv_bfloat16*)(base + OFF_BHI);
    __nv_bfloat16* blo = (__nv_bfloat16*)(base + OFF_BLO);
    float* FL = (float*)(base + OFF_FL);
    float* gx     = FL + FO_GX;
    float* gh     = FL + FO_GH;
    float* hnew   = FL + FO_HNEW;
    float* denc   = FL + FO_DENC;
    float* dtgt   = FL + FO_DTGT;
    float* sstate = FL + FO_SSTATE;
    float* cptr   = FL + FO_CPTR;
    float* ctptr  = FL + FO_CTPTR;
    float* ctxe   = FL + FO_CTXE;
    float* ctxt   = FL + FO_CTXT;
    float* sc_e   = FL + FO_SCE;
    float* sc_t   = FL + FO_SCT;
    float* at_e   = FL + FO_ATE;
    float* at_t   = FL + FO_ATT;

    // Attribute cache: set once on the (uncaptured) correctness call; avoids
    // non-stream API calls during graph capture. (Pattern passed in R4/R7.)
    static bool attr_done = false;
    if (!attr_done) {
        cudaFuncSetAttribute(big_mma_k, cudaFuncAttributeMaxDynamicSharedMemorySize,
                             SMEM_BIG);
        attr_done = true;
    }

    // conversions
    convert_stat_k<<<32768, 256>>>(stat, (__nv_bfloat162*)shi, (__nv_bfloat162*)slo);
    convert_w_k<<<768, 256>>>(encW, tgtW, ptrW, (__nv_bfloat162*)bhi, (__nv_bfloat162*)blo);

    // GRU input/hidden GEMMs (z-batched)
    small_gemm3_k<<<dim3(24, 4, 2), 256>>>(
        dech, wih, 512, 0, gx, 1536,
        lhh,  whh, 512, 0, gh, 1536,
        lhh,  whh, 512, 0, gh, 1536);
    gru_gates_k<<<256, 256>>>(gx, gh, bih, bhh, lhh, hnew, out + 65536);

    // per-batch bias projections (z-batched)
    small_gemm3_k<<<dim3(8, 4, 3), 256>>>(
        hnew, encW, 1024, 512,  denc,   512,
        tgth, tgtW, 1024, 512,  dtgt,   512,
        semb, ptrW, 1536, 1024, sstate, 512);

    // big tensor-core GEMM: enc scores, tgt scores, S_ptr (transposed)
    big_mma_k<<<dim3(3, 512), 256, SMEM_BIG>>>(shi, slo, bhi, blo, denc, dtgt,
                                               encv, tgtv, sc_e, sc_t, SbigT);

    // softmax + contexts + context projections (z-batched)
    softmax_k<<<256, 256>>>(sc_e, sc_t, at_e, at_t);
    context_k<<<512, 128>>>(stat, at_e, at_t, ctxe, ctxt);
    small_gemm3_k<<<dim3(8, 4, 2), 256>>>(
        ctxe, ptrW, 1536, 512, cptr,  512,
        ctxt, ptrW, 1536, 512, ctptr, 512,
        ctxt, ptrW, 1536, 512, ctptr, 512);

    // final pointer scores
    final_k<<<256, 256>>>(SbigT, cptr, ctptr, sstate, ptrv, out);
}

// round 11
// speedup vs baseline: 3.6339x; 1.9368x over previous
#include <cuda_runtime.h>
#include <cuda_fp16.h>

// ===========================================================================
// B=128, N=512, H=512.  Output: [probs 65536 | new_last_hh 65536] fp32
// Big GEMM: single-term fp16 mma.sync + ldmatrix (sm_103-safe; legacy-HMMA-
// rate bound, so minimize MMA instruction count).  R10 + ring-slot fix.
// ===========================================================================

// -------------------- scratch (byte offsets) --------------------------------
#define OFF_SBIGT  0L                       // 512*65536 f32 (S_ptr, [h][row])
#define OFF_SH     134217728L               // stat fp16 [65536][512]
#define OFF_BH     201326592L               // Bcat fp16 [1536][512]
#define OFF_FL     202899456L               // float region
#define SCRATCH_BYTES (OFF_FL + 4718592L)
__device__ __align__(1024) unsigned char g_scratch[SCRATCH_BYTES];

// float sub-offsets (in floats) inside FL region
#define FO_GX     0L
#define FO_GH     196608L
#define FO_HNEW   393216L
#define FO_DENC   458752L
#define FO_DTGT   524288L
#define FO_SSTATE 589824L
#define FO_CPTR   655360L
#define FO_CTPTR  720896L
#define FO_CTXE   786432L
#define FO_CTXT   851968L
#define FO_SCE    917504L
#define FO_SCT    983040L
#define FO_ATE    1048576L
#define FO_ATT    1114112L

// ===================== PTX helpers (baseline ISA only) ======================
__device__ __forceinline__ unsigned smem_u32(const void* p) {
    unsigned a;
    asm("{ .reg .u64 t; cvta.to.shared.u64 t, %1; cvt.u32.u64 %0, t; }"
        : "=r"(a) : "l"(p));
    return a;
}
__device__ __forceinline__ void cp16(unsigned dst, const void* src) {
    asm volatile("cp.async.cg.shared.global [%0], [%1], 16;" :: "r"(dst), "l"(src));
}
#define CP_COMMIT() asm volatile("cp.async.commit_group;" ::: "memory")
#define CP_WAIT2()  asm volatile("cp.async.wait_group 2;" ::: "memory")
#define CP_WAIT1()  asm volatile("cp.async.wait_group 1;" ::: "memory")
#define CP_WAIT0()  asm volatile("cp.async.wait_group 0;" ::: "memory")

__device__ __forceinline__ void mma16816(float c[4],
        unsigned a0, unsigned a1, unsigned a2, unsigned a3,
        unsigned b0, unsigned b1) {
    asm volatile(
        "mma.sync.aligned.m16n8k16.row.col.f32.f16.f16.f32 "
        "{%0,%1,%2,%3}, {%4,%5,%6,%7}, {%8,%9}, {%0,%1,%2,%3};"
        : "+f"(c[0]), "+f"(c[1]), "+f"(c[2]), "+f"(c[3])
        : "r"(a0), "r"(a1), "r"(a2), "r"(a3), "r"(b0), "r"(b1));
}
__device__ __forceinline__ void ldsm4(unsigned r[4], unsigned addr) {
    asm volatile("ldmatrix.sync.aligned.m8n8.x4.shared.b16 {%0,%1,%2,%3}, [%4];"
        : "=r"(r[0]), "=r"(r[1]), "=r"(r[2]), "=r"(r[3]) : "r"(addr));
}

// ===========================================================================
// fp32 -> fp16 conversions
// ===========================================================================
__global__ void __launch_bounds__(256)
convert_stat_k(const float* __restrict__ x, __half2* __restrict__ h)
{
    size_t i = (size_t)blockIdx.x * 256 + threadIdx.x;   // 8388608 quads
    float4 v = ((const float4*)x)[i];
    h[2 * i]     = __floats2half2_rn(v.x, v.y);
    h[2 * i + 1] = __floats2half2_rn(v.z, v.w);
}

// Bcat[1536][512]: rows 0-511 encW static, 512-1023 tgtW static, 1024-1535 ptrW static
__global__ void __launch_bounds__(256)
convert_w_k(const float* __restrict__ encW, const float* __restrict__ tgtW,
            const float* __restrict__ ptrW, __half2* __restrict__ h)
{
    int i = blockIdx.x * 256 + threadIdx.x;              // 196608 quads
    int e = i * 4;
    int row = e >> 9, k = e & 511;
    const float* src;
    if (row < 512)       src = encW + (size_t)row * 1024 + k;
    else if (row < 1024) src = tgtW + (size_t)(row - 512) * 1024 + k;
    else                 src = ptrW + (size_t)(row - 1024) * 1536 + k;
    float4 v = *(const float4*)src;
    h[2 * i]     = __floats2half2_rn(v.x, v.y);
    h[2 * i + 1] = __floats2half2_rn(v.z, v.w);
}

// ===========================================================================
// Small GEMM, z-batched: up to 3 independent C[128 x N] = A[128x512] @ W^T
// tile 32 rows x 64 cols, 256 threads, grid (N/64, 4, nz)
// ===========================================================================
__global__ void __launch_bounds__(256)
small_gemm3_k(const float* A0, const float* W0, int ldw0, int wofs0, float* C0, int ldc0,
              const float* A1, const float* W1, int ldw1, int wofs1, float* C1, int ldc1,
              const float* A2, const float* W2, int ldw2, int wofs2, float* C2, int ldc2)
{
    int z = blockIdx.z;
    const float* A = (z == 0) ? A0 : (z == 1) ? A1 : A2;
    const float* W = (z == 0) ? W0 : (z == 1) ? W1 : W2;
    int ldw  = (z == 0) ? ldw0  : (z == 1) ? ldw1  : ldw2;
    int wofs = (z == 0) ? wofs0 : (z == 1) ? wofs1 : wofs2;
    float* C = (z == 0) ? C0 : (z == 1) ? C1 : C2;
    int ldc  = (z == 0) ? ldc0 : (z == 1) ? ldc1 : ldc2;

    __shared__ float As[32][33];
    __shared__ float Ws[64][33];
    int t = threadIdx.x;
    int c = t & 63, rg = t >> 6;
    int row0 = blockIdx.y * 32, col0 = blockIdx.x * 64;
    float acc[8];
#pragma unroll
    for (int i = 0; i < 8; i++) acc[i] = 0.f;

    for (int k0 = 0; k0 < 512; k0 += 32) {
        {
            int idx = t * 4, row = idx >> 5, kk = idx & 31;
            float4 v = *(const float4*)(A + (size_t)(row0 + row) * 512 + k0 + kk);
            As[row][kk] = v.x; As[row][kk + 1] = v.y;
            As[row][kk + 2] = v.z; As[row][kk + 3] = v.w;
        }
        {
            int idx = t * 8, row = idx >> 5, kk = idx & 31;
            const float* s = W + (size_t)(col0 + row) * ldw + wofs + k0 + kk;
            float4 v0 = *(const float4*)s;
            float4 v1 = *(const float4*)(s + 4);
            Ws[row][kk] = v0.x; Ws[row][kk + 1] = v0.y;
            Ws[row][kk + 2] = v0.z; Ws[row][kk + 3] = v0.w;
            Ws[row][kk + 4] = v1.x; Ws[row][kk + 5] = v1.y;
            Ws[row][kk + 6] = v1.z; Ws[row][kk + 7] = v1.w;
        }
        __syncthreads();
#pragma unroll
        for (int kk = 0; kk < 32; kk++) {
            float wv = Ws[c][kk];
#pragma unroll
            for (int i = 0; i < 8; i++)
                acc[i] += As[rg * 8 + i][kk] * wv;
        }
        __syncthreads();
    }
#pragma unroll
    for (int i = 0; i < 8; i++)
        C[(size_t)(row0 + rg * 8 + i) * ldc + col0 + c] = acc[i];
}

// ===========================================================================
__global__ void gru_gates_k(const float* __restrict__ gx, const float* __restrict__ gh,
                            const float* __restrict__ bih, const float* __restrict__ bhh,
                            const float* __restrict__ lhh,
                            float* __restrict__ hnew, float* __restrict__ outh)
{
    int i = blockIdx.x * blockDim.x + threadIdx.x;
    int b = i >> 9, j = i & 511;
    const float* gxb = gx + b * 1536;
    const float* ghb = gh + b * 1536;
    float xr = gxb[j] + bih[j],              hr = ghb[j] + bhh[j];
    float xz = gxb[512 + j] + bih[512 + j],  hz = ghb[512 + j] + bhh[512 + j];
    float xn = gxb[1024 + j] + bih[1024 + j];
    float hn = ghb[1024 + j] + bhh[1024 + j];
    float r = 1.f / (1.f + expf(-(xr + hr)));
    float z = 1.f / (1.f + expf(-(xz + hz)));
    float n = tanhf(xn + r * hn);
    float h = lhh[i];
    float v = (1.f - z) * n + z * h;
    hnew[i] = v;
    outh[i] = v;
}

// ===========================================================================
// Big fused tensor-core GEMM (single-term fp16 mma.sync + ldmatrix).
// grid (3, 512): g = {enc, tgt, ptr}, 128 rows per CTA, N=512 via 4 ht-tiles.
// 3-stage cp.async ring; slot for stage s is (s % 3) * STAGE_B.
// SMEM: [0,61440) 3 stages x (A tile + B tile), tile = 128 rows x 80B (64B data)
//       overlay [0,67584): transpose tile 128x132 f32 (ptr epilogue)
//       [61440) DV 512f, [63488) VV 512f, [65536) RED 4x128 f
// ===========================================================================
#define TILE_B   10240
#define STAGE_B  20480
#define SM_DV    61440
#define SM_VV    63488
#define SM_RED   65536
#define SMEM_BIG 67584

__device__ __forceinline__ void load_stage(
    unsigned sbase, unsigned bufbase, int kt, int t, int row0, int grow,
    const __half* __restrict__ sh, const __half* __restrict__ bh)
{
    int tsel = t >> 7;           // 0:A 1:B
    int tt = t & 127;
    const __half* base = tsel ? bh : sh;
    int roff = tsel ? grow : row0;
    unsigned stile = sbase + bufbase + (unsigned)(tsel * TILE_B) + (unsigned)(tt * 80);
    const __half* src = base + (size_t)(roff + tt) * 512 + kt * 32;
#pragma unroll
    for (int c = 0; c < 4; c++)
        cp16(stile + (unsigned)(c * 16), src + c * 8);
}

__global__ void __launch_bounds__(256, 2)
big_mma_k(const __half* __restrict__ sh, const __half* __restrict__ bh,
          const float* __restrict__ denc, const float* __restrict__ dtgt,
          const float* __restrict__ encv, const float* __restrict__ tgtv,
          float* __restrict__ sc_e, float* __restrict__ sc_t,
          float* __restrict__ SbigT)
{
    extern __shared__ __align__(128) unsigned char smem[];
    unsigned sbase = smem_u32(smem);
    int t = threadIdx.x;
    int lane = t & 31, wid = t >> 5;
    int wm = wid & 1, wn = wid >> 1;         // warp tile: rows wm*64, cols wn*32
    int qr = lane >> 2, qc = lane & 3;
    int g = blockIdx.x;
    int row0 = blockIdx.y * 128;
    int b = blockIdx.y >> 2;
    int grow = g * 512;

    // ldmatrix lane address components (same mapping as proven R9 kernel)
    int lrow = lane & 7, lsel = lane >> 3;
    unsigned a_off = (unsigned)((wm * 64 + (lsel & 1) * 8 + lrow) * 80 + (lsel >> 1) * 16);
    unsigned b_off = (unsigned)((wn * 32 + (lsel >> 1) * 8 + lrow) * 80 + (lsel & 1) * 16);

    float* DV  = (float*)(smem + SM_DV);
    float* VV  = (float*)(smem + SM_VV);
    float* RED = (float*)(smem + SM_RED);
    if (g < 2) {
        const float* dsrc = g ? dtgt : denc;
        const float* vsrc = g ? tgtv : encv;
        for (int i = t; i < 512; i += 256) { DV[i] = dsrc[b * 512 + i]; VV[i] = vsrc[i]; }
    }

    float sacc[4][2];
#pragma unroll
    for (int i = 0; i < 4; i++) { sacc[i][0] = 0.f; sacc[i][1] = 0.f; }

    for (int ht = 0; ht < 4; ht++) {
        int gr = grow + ht * 128;
        float acc[4][4][4];
#pragma unroll
        for (int mi = 0; mi < 4; mi++)
#pragma unroll
            for (int nj = 0; nj < 4; nj++)
#pragma unroll
                for (int r = 0; r < 4; r++) acc[mi][nj][r] = 0.f;

        // prologue: stage 0 -> slot 0, stage 1 -> slot 1
        load_stage(sbase, 0, 0, t, row0, gr, sh, bh);
        CP_COMMIT();
        load_stage(sbase, STAGE_B, 1, t, row0, gr, sh, bh);
        CP_COMMIT();

        for (int kt = 0; kt < 16; kt++) {
            unsigned buf = (unsigned)((kt % 3) * STAGE_B);      // slot of stage kt
            if (kt + 2 < 16) {
                unsigned nslot = (unsigned)(((kt + 2) % 3) * STAGE_B);
                load_stage(sbase, nslot, kt + 2, t, row0, gr, sh, bh);
                CP_COMMIT();
                CP_WAIT2();                                      // stage kt complete
            } else if (kt + 1 < 16) {
                CP_WAIT1();
            } else {
                CP_WAIT0();
            }
            __syncthreads();

            unsigned A = sbase + buf;
            unsigned B = A + TILE_B;

#pragma unroll
            for (int k16 = 0; k16 < 2; k16++) {
                unsigned kb = (unsigned)(k16 * 32);
                unsigned a[4][4], bb[2][4];
#pragma unroll
                for (int mi = 0; mi < 4; mi++)
                    ldsm4(a[mi], A + a_off + mi * 1280 + kb);
#pragma unroll
                for (int np = 0; np < 2; np++)
                    ldsm4(bb[np], B + b_off + np * 1280 + kb);
#pragma unroll
                for (int mi = 0; mi < 4; mi++)
#pragma unroll
                    for (int nj = 0; nj < 4; nj++)
                        mma16816(acc[mi][nj], a[mi][0], a[mi][1], a[mi][2], a[mi][3],
                                 bb[nj >> 1][(nj & 1) * 2], bb[nj >> 1][(nj & 1) * 2 + 1]);
            }
            __syncthreads();
        }

        // ---------------- per-ht epilogue ----------------
        if (g < 2) {
#pragma unroll
            for (int mi = 0; mi < 4; mi++)
#pragma unroll
                for (int nj = 0; nj < 4; nj++) {
                    int c0 = ht * 128 + wn * 32 + nj * 8 + qc * 2;
                    float d0 = DV[c0], d1 = DV[c0 + 1];
                    float v0 = VV[c0], v1 = VV[c0 + 1];
                    sacc[mi][0] += v0 * tanhf(acc[mi][nj][0] + d0)
                                 + v1 * tanhf(acc[mi][nj][1] + d1);
                    sacc[mi][1] += v0 * tanhf(acc[mi][nj][2] + d0)
                                 + v1 * tanhf(acc[mi][nj][3] + d1);
                }
        } else {
            float* T = (float*)smem;         // overlay (post-sync, pre-next-prologue)
#pragma unroll
            for (int mi = 0; mi < 4; mi++)
#pragma unroll
                for (int nj = 0; nj < 4; nj++) {
                    int cl = wn * 32 + nj * 8 + qc * 2;
                    int rl = wm * 64 + mi * 16 + qr;
                    T[cl * 132 + rl]           = acc[mi][nj][0];
                    T[(cl + 1) * 132 + rl]     = acc[mi][nj][1];
                    T[cl * 132 + rl + 8]       = acc[mi][nj][2];
                    T[(cl + 1) * 132 + rl + 8] = acc[mi][nj][3];
                }
            __syncthreads();
#pragma unroll 1
            for (int c = wid * 16; c < wid * 16 + 16; c++) {
                float4 v = *(const float4*)(T + c * 132 + lane * 4);
                *(float4*)(SbigT + (size_t)(ht * 128 + c) * 65536 + row0 + lane * 4) = v;
            }
            __syncthreads();
        }
    }

    if (g < 2) {
#pragma unroll
        for (int mi = 0; mi < 4; mi++) {
#pragma unroll
            for (int h = 0; h < 2; h++) {
                float s = sacc[mi][h];
                s += __shfl_xor_sync(0xffffffffu, s, 1);
                s += __shfl_xor_sync(0xffffffffu, s, 2);
                sacc[mi][h] = s;
            }
        }
        if (qc == 0) {
#pragma unroll
            for (int mi = 0; mi < 4; mi++) {
                int r = wm * 64 + mi * 16 + qr;
                RED[wn * 128 + r]     = sacc[mi][0];
                RED[wn * 128 + r + 8] = sacc[mi][1];
            }
        }
        __syncthreads();
        if (t < 128) {
            float s = RED[t] + RED[128 + t] + RED[256 + t] + RED[384 + t];
            (g ? sc_t : sc_e)[row0 + t] = s;
        }
    }
}

// ===========================================================================
__global__ void softmax_k(const float* __restrict__ score_e, const float* __restrict__ score_t,
                          float* __restrict__ attn_e, float* __restrict__ attn_t)
{
    int b = blockIdx.x & 127;
    int wh = blockIdx.x >> 7;
    const float* src = (wh ? score_t : score_e) + b * 512;
    float* dst = (wh ? attn_t : attn_e) + b * 512;
    int t = threadIdx.x;
    float v0 = src[t], v1 = src[t + 256];
    __shared__ float red[256];
    red[t] = fmaxf(v0, v1);
    __syncthreads();
    for (int s = 128; s > 0; s >>= 1) {
        if (t < s) red[t] = fmaxf(red[t], red[t + s]);
        __syncthreads();
    }
    float mx = red[0];
    __syncthreads();
    float e0 = expf(v0 - mx), e1 = expf(v1 - mx);
    red[t] = e0 + e1;
    __syncthreads();
    for (int s = 128; s > 0; s >>= 1) {
        if (t < s) red[t] += red[t + s];
        __syncthreads();
    }
    float inv = 1.f / red[0];
    dst[t] = e0 * inv;
    dst[t + 256] = e1 * inv;
}

__global__ void context_k(const float* __restrict__ stat,
                          const float* __restrict__ ae, const float* __restrict__ at,
                          float* __restrict__ ce, float* __restrict__ ct)
{
    int b = blockIdx.x >> 2;
    int ch = blockIdx.x & 3;
    int h = ch * 128 + threadIdx.x;
    __shared__ float sae[512], sat[512];
    for (int i = threadIdx.x; i < 512; i += 128) {
        sae[i] = ae[b * 512 + i];
        sat[i] = at[b * 512 + i];
    }
    __syncthreads();
    const float* Sb = stat + (size_t)b * 262144 + h;
    float se = 0.f, st = 0.f;
#pragma unroll 8
    for (int n = 0; n < 512; n++) {
        float sv = Sb[(size_t)n * 512];
        se += sae[n] * sv;
        st += sat[n] * sv;
    }
    ce[b * 512 + h] = se;
    ct[b * 512 + h] = st;
}

// Final pointer scores from transposed S: fully coalesced reads.
__global__ void __launch_bounds__(256)
final_k(const float* __restrict__ SbigT,
        const float* __restrict__ cp, const float* __restrict__ ctp,
        const float* __restrict__ ss, const float* __restrict__ vp,
        float* __restrict__ out)
{
    __shared__ float a1[512], a2[512], vv[512];
    int b = blockIdx.x >> 1;                 // 256 blocks, 2 per batch
    int t = threadIdx.x;
    for (int i = t; i < 512; i += 256) {
        float s0 = ss[b * 512 + i];
        a1[i] = cp[b * 512 + i] + s0;
        a2[i] = ctp[b * 512 + i] + s0;
        vv[i] = vp[i];
    }
    __syncthreads();
    int row = blockIdx.x * 256 + t;
    float s1 = 0.f, s2 = 0.f;
#pragma unroll 4
    for (int h = 0; h < 512; h++) {
        float x = __ldg(SbigT + (size_t)h * 65536 + row);
        float v = vv[h];
        s1 += v * tanhf(x + a1[h]);
        s2 += v * tanhf(x + a2[h]);
    }
    out[row] = 5.0f * s1 + s2;
}

// ===========================================================================
extern "C" void kernel_launch(void* const* d_in, const int* in_sizes, int n_in,
                              void* d_out, int out_size)
{
    const float* stat = (const float*)d_in[0];   // (128,512,512)
    const float* semb = (const float*)d_in[1];   // (128,1,512)
    const float* dech = (const float*)d_in[2];   // (128,1,512)
    const float* tgth = (const float*)d_in[3];   // (128,1,512)
    const float* lhh  = (const float*)d_in[4];   // (1,128,512)
    const float* ptrv = (const float*)d_in[5];   // (1,1,512)
    const float* ptrW = (const float*)d_in[6];   // (1,512,1536)
    const float* encv = (const float*)d_in[7];   // (1,1,512)
    const float* encW = (const float*)d_in[8];   // (1,512,1024)
    const float* tgtv = (const float*)d_in[9];   // (1,1,512)
    const float* tgtW = (const float*)d_in[10];  // (1,512,1024)
    const float* wih  = (const float*)d_in[11];  // (1536,512)
    const float* whh  = (const float*)d_in[12];  // (1536,512)
    const float* bih  = (const float*)d_in[13];
    const float* bhh  = (const float*)d_in[14];
    float* out = (float*)d_out;

    unsigned char* base = nullptr;
    cudaGetSymbolAddress((void**)&base, g_scratch);
    float* SbigT = (float*)(base + OFF_SBIGT);
    __half* sh = (__half*)(base + OFF_SH);
    __half* bhp = (__half*)(base + OFF_BH);
    float* FL = (float*)(base + OFF_FL);
    float* gx     = FL + FO_GX;
    float* gh     = FL + FO_GH;
    float* hnew   = FL + FO_HNEW;
    float* denc   = FL + FO_DENC;
    float* dtgt   = FL + FO_DTGT;
    float* sstate = FL + FO_SSTATE;
    float* cptr   = FL + FO_CPTR;
    float* ctptr  = FL + FO_CTPTR;
    float* ctxe   = FL + FO_CTXE;
    float* ctxt   = FL + FO_CTXT;
    float* sc_e   = FL + FO_SCE;
    float* sc_t   = FL + FO_SCT;
    float* at_e   = FL + FO_ATE;
    float* at_t   = FL + FO_ATT;

    // Attribute cache: set once on the (uncaptured) correctness call; avoids
    // non-stream API calls during graph capture. (Pattern passed R4/R7/R9.)
    static bool attr_done = false;
    if (!attr_done) {
        cudaFuncSetAttribute(big_mma_k, cudaFuncAttributeMaxDynamicSharedMemorySize,
                             SMEM_BIG);
        attr_done = true;
    }

    // conversions
    convert_stat_k<<<32768, 256>>>(stat, (__half2*)sh);
    convert_w_k<<<768, 256>>>(encW, tgtW, ptrW, (__half2*)bhp);

    // GRU input/hidden GEMMs (z-batched)
    small_gemm3_k<<<dim3(24, 4, 2), 256>>>(
        dech, wih, 512, 0, gx, 1536,
        lhh,  whh, 512, 0, gh, 1536,
        lhh,  whh, 512, 0, gh, 1536);
    gru_gates_k<<<256, 256>>>(gx, gh, bih, bhh, lhh, hnew, out + 65536);

    // per-batch bias projections (z-batched)
    small_gemm3_k<<<dim3(8, 4, 3), 256>>>(
        hnew, encW, 1024, 512,  denc,   512,
        tgth, tgtW, 1024, 512,  dtgt,   512,
        semb, ptrW, 1536, 1024, sstate, 512);

    // big tensor-core GEMM: enc scores, tgt scores, S_ptr (transposed)
    big_mma_k<<<dim3(3, 512), 256, SMEM_BIG>>>(sh, bhp, denc, dtgt,
                                               encv, tgtv, sc_e, sc_t, SbigT);

    // softmax + contexts + context projections (z-batched)
    softmax_k<<<256, 256>>>(sc_e, sc_t, at_e, at_t);
    context_k<<<512, 128>>>(stat, at_e, at_t, ctxe, ctxt);
    small_gemm3_k<<<dim3(8, 4, 2), 256>>>(
        ctxe, ptrW, 1536, 512, cptr,  512,
        ctxt, ptrW, 1536, 512, ctptr, 512,
        ctxt, ptrW, 1536, 512, ctptr, 512);

    // final pointer scores
    final_k<<<256, 256>>>(SbigT, cptr, ctptr, sstate, ptrv, out);
}

// round 12
// speedup vs baseline: 4.1407x; 1.1395x over previous
#include <cuda_runtime.h>
#include <cuda_fp16.h>

// ===========================================================================
// B=128, N=512, H=512.  Output: [probs 65536 | new_last_hh 65536] fp32
// Big GEMM: single-term fp16 mma.sync + ldmatrix (legacy-HMMA-rate bound).
// R11 + two-launch split: ptr group fuses the final pointer-score epilogue,
// eliminating the 134MB SbigT round-trip and final_k.
// ===========================================================================

// -------------------- scratch (byte offsets) --------------------------------
#define OFF_SH     0L                       // stat fp16 [65536][512]
#define OFF_BH     67108864L                // Bcat fp16 [1536][512]
#define OFF_FL     68681728L                // float region
#define SCRATCH_BYTES (OFF_FL + 4718592L)
__device__ __align__(1024) unsigned char g_scratch[SCRATCH_BYTES];

// float sub-offsets (in floats) inside FL region
#define FO_GX     0L
#define FO_GH     196608L
#define FO_HNEW   393216L
#define FO_DENC   458752L
#define FO_DTGT   524288L
#define FO_SSTATE 589824L
#define FO_CPTR   655360L
#define FO_CTPTR  720896L
#define FO_CTXE   786432L
#define FO_CTXT   851968L
#define FO_SCE    917504L
#define FO_SCT    983040L
#define FO_ATE    1048576L
#define FO_ATT    1114112L

// ===================== PTX helpers (baseline ISA only) ======================
__device__ __forceinline__ unsigned smem_u32(const void* p) {
    unsigned a;
    asm("{ .reg .u64 t; cvta.to.shared.u64 t, %1; cvt.u32.u64 %0, t; }"
        : "=r"(a) : "l"(p));
    return a;
}
__device__ __forceinline__ void cp16(unsigned dst, const void* src) {
    asm volatile("cp.async.cg.shared.global [%0], [%1], 16;" :: "r"(dst), "l"(src));
}
#define CP_COMMIT() asm volatile("cp.async.commit_group;" ::: "memory")
#define CP_WAIT2()  asm volatile("cp.async.wait_group 2;" ::: "memory")
#define CP_WAIT1()  asm volatile("cp.async.wait_group 1;" ::: "memory")
#define CP_WAIT0()  asm volatile("cp.async.wait_group 0;" ::: "memory")

__device__ __forceinline__ void mma16816(float c[4],
        unsigned a0, unsigned a1, unsigned a2, unsigned a3,
        unsigned b0, unsigned b1) {
    asm volatile(
        "mma.sync.aligned.m16n8k16.row.col.f32.f16.f16.f32 "
        "{%0,%1,%2,%3}, {%4,%5,%6,%7}, {%8,%9}, {%0,%1,%2,%3};"
        : "+f"(c[0]), "+f"(c[1]), "+f"(c[2]), "+f"(c[3])
        : "r"(a0), "r"(a1), "r"(a2), "r"(a3), "r"(b0), "r"(b1));
}
__device__ __forceinline__ void ldsm4(unsigned r[4], unsigned addr) {
    asm volatile("ldmatrix.sync.aligned.m8n8.x4.shared.b16 {%0,%1,%2,%3}, [%4];"
        : "=r"(r[0]), "=r"(r[1]), "=r"(r[2]), "=r"(r[3]) : "r"(addr));
}

// ===========================================================================
// fp32 -> fp16 conversions
// ===========================================================================
__global__ void __launch_bounds__(256)
convert_stat_k(const float* __restrict__ x, __half2* __restrict__ h)
{
    size_t i = (size_t)blockIdx.x * 256 + threadIdx.x;   // 8388608 quads
    float4 v = ((const float4*)x)[i];
    h[2 * i]     = __floats2half2_rn(v.x, v.y);
    h[2 * i + 1] = __floats2half2_rn(v.z, v.w);
}

// Bcat[1536][512]: rows 0-511 encW static, 512-1023 tgtW static, 1024-1535 ptrW static
__global__ void __launch_bounds__(256)
convert_w_k(const float* __restrict__ encW, const float* __restrict__ tgtW,
            const float* __restrict__ ptrW, __half2* __restrict__ h)
{
    int i = blockIdx.x * 256 + threadIdx.x;              // 196608 quads
    int e = i * 4;
    int row = e >> 9, k = e & 511;
    const float* src;
    if (row < 512)       src = encW + (size_t)row * 1024 + k;
    else if (row < 1024) src = tgtW + (size_t)(row - 512) * 1024 + k;
    else                 src = ptrW + (size_t)(row - 1024) * 1536 + k;
    float4 v = *(const float4*)src;
    h[2 * i]     = __floats2half2_rn(v.x, v.y);
    h[2 * i + 1] = __floats2half2_rn(v.z, v.w);
}

// ===========================================================================
// Small GEMM, z-batched: up to 3 independent C[128 x N] = A[128x512] @ W^T
// tile 32 rows x 64 cols, 256 threads, grid (N/64, 4, nz)
// ===========================================================================
__global__ void __launch_bounds__(256)
small_gemm3_k(const float* A0, const float* W0, int ldw0, int wofs0, float* C0, int ldc0,
              const float* A1, const float* W1, int ldw1, int wofs1, float* C1, int ldc1,
              const float* A2, const float* W2, int ldw2, int wofs2, float* C2, int ldc2)
{
    int z = blockIdx.z;
    const float* A = (z == 0) ? A0 : (z == 1) ? A1 : A2;
    const float* W = (z == 0) ? W0 : (z == 1) ? W1 : W2;
    int ldw  = (z == 0) ? ldw0  : (z == 1) ? ldw1  : ldw2;
    int wofs = (z == 0) ? wofs0 : (z == 1) ? wofs1 : wofs2;
    float* C = (z == 0) ? C0 : (z == 1) ? C1 : C2;
    int ldc  = (z == 0) ? ldc0 : (z == 1) ? ldc1 : ldc2;

    __shared__ float As[32][33];
    __shared__ float Ws[64][33];
    int t = threadIdx.x;
    int c = t & 63, rg = t >> 6;
    int row0 = blockIdx.y * 32, col0 = blockIdx.x * 64;
    float acc[8];
#pragma unroll
    for (int i = 0; i < 8; i++) acc[i] = 0.f;

    for (int k0 = 0; k0 < 512; k0 += 32) {
        {
            int idx = t * 4, row = idx >> 5, kk = idx & 31;
            float4 v = *(const float4*)(A + (size_t)(row0 + row) * 512 + k0 + kk);
            As[row][kk] = v.x; As[row][kk + 1] = v.y;
            As[row][kk + 2] = v.z; As[row][kk + 3] = v.w;
        }
        {
            int idx = t * 8, row = idx >> 5, kk = idx & 31;
            const float* s = W + (size_t)(col0 + row) * ldw + wofs + k0 + kk;
            float4 v0 = *(const float4*)s;
            float4 v1 = *(const float4*)(s + 4);
            Ws[row][kk] = v0.x; Ws[row][kk + 1] = v0.y;
            Ws[row][kk + 2] = v0.z; Ws[row][kk + 3] = v0.w;
            Ws[row][kk + 4] = v1.x; Ws[row][kk + 5] = v1.y;
            Ws[row][kk + 6] = v1.z; Ws[row][kk + 7] = v1.w;
        }
        __syncthreads();
#pragma unroll
        for (int kk = 0; kk < 32; kk++) {
            float wv = Ws[c][kk];
#pragma unroll
            for (int i = 0; i < 8; i++)
                acc[i] += As[rg * 8 + i][kk] * wv;
        }
        __syncthreads();
    }
#pragma unroll
    for (int i = 0; i < 8; i++)
        C[(size_t)(row0 + rg * 8 + i) * ldc + col0 + c] = acc[i];
}

// ===========================================================================
__global__ void gru_gates_k(const float* __restrict__ gx, const float* __restrict__ gh,
                            const float* __restrict__ bih, const float* __restrict__ bhh,
                            const float* __restrict__ lhh,
                            float* __restrict__ hnew, float* __restrict__ outh)
{
    int i = blockIdx.x * blockDim.x + threadIdx.x;
    int b = i >> 9, j = i & 511;
    const float* gxb = gx + b * 1536;
    const float* ghb = gh + b * 1536;
    float xr = gxb[j] + bih[j],              hr = ghb[j] + bhh[j];
    float xz = gxb[512 + j] + bih[512 + j],  hz = ghb[512 + j] + bhh[512 + j];
    float xn = gxb[1024 + j] + bih[1024 + j];
    float hn = ghb[1024 + j] + bhh[1024 + j];
    float r = 1.f / (1.f + expf(-(xr + hr)));
    float z = 1.f / (1.f + expf(-(xz + hz)));
    float n = tanhf(xn + r * hn);
    float h = lhh[i];
    float v = (1.f - z) * n + z * h;
    hnew[i] = v;
    outh[i] = v;
}

// ===========================================================================
// Shared mainloop constants.
// SMEM: [0,61440) 3 stages x (A tile + B tile), tile = 128 rows x 80B (64B data)
// ===========================================================================
#define TILE_B   10240
#define STAGE_B  20480
// et kernel extras
#define SM_DV    61440
#define SM_VV    63488
#define SM_RED   65536
#define SMEM_ET  67584
// ptr kernel extras
#define SM_A1    61440
#define SM_A2    63488
#define SM_PV    65536
#define SM_RED2  67584
#define SMEM_PTR 71680

__device__ __forceinline__ void load_stage(
    unsigned sbase, unsigned bufbase, int kt, int t, int row0, int grow,
    const __half* __restrict__ sh, const __half* __restrict__ bh)
{
    int tsel = t >> 7;           // 0:A 1:B
    int tt = t & 127;
    const __half* base = tsel ? bh : sh;
    int roff = tsel ? grow : row0;
    unsigned stile = sbase + bufbase + (unsigned)(tsel * TILE_B) + (unsigned)(tt * 80);
    const __half* src = base + (size_t)(roff + tt) * 512 + kt * 32;
#pragma unroll
    for (int c = 0; c < 4; c++)
        cp16(stile + (unsigned)(c * 16), src + c * 8);
}

// ===========================================================================
// enc/tgt GEMM + score epilogue.  grid (2, 512): g = {enc, tgt}
// ===========================================================================
__global__ void __launch_bounds__(256, 2)
big_mma_et_k(const __half* __restrict__ sh, const __half* __restrict__ bh,
             const float* __restrict__ denc, const float* __restrict__ dtgt,
             const float* __restrict__ encv, const float* __restrict__ tgtv,
             float* __restrict__ sc_e, float* __restrict__ sc_t)
{
    extern __shared__ __align__(128) unsigned char smem[];
    unsigned sbase = smem_u32(smem);
    int t = threadIdx.x;
    int lane = t & 31, wid = t >> 5;
    int wm = wid & 1, wn = wid >> 1;
    int qr = lane >> 2, qc = lane & 3;
    int g = blockIdx.x;
    int row0 = blockIdx.y * 128;
    int b = blockIdx.y >> 2;
    int grow = g * 512;

    int lrow = lane & 7, lsel = lane >> 3;
    unsigned a_off = (unsigned)((wm * 64 + (lsel & 1) * 8 + lrow) * 80 + (lsel >> 1) * 16);
    unsigned b_off = (unsigned)((wn * 32 + (lsel >> 1) * 8 + lrow) * 80 + (lsel & 1) * 16);

    float* DV  = (float*)(smem + SM_DV);
    float* VV  = (float*)(smem + SM_VV);
    float* RED = (float*)(smem + SM_RED);
    {
        const float* dsrc = g ? dtgt : denc;
        const float* vsrc = g ? tgtv : encv;
        for (int i = t; i < 512; i += 256) { DV[i] = dsrc[b * 512 + i]; VV[i] = vsrc[i]; }
    }

    float sacc[4][2];
#pragma unroll
    for (int i = 0; i < 4; i++) { sacc[i][0] = 0.f; sacc[i][1] = 0.f; }

    for (int ht = 0; ht < 4; ht++) {
        int gr = grow + ht * 128;
        float acc[4][4][4];
#pragma unroll
        for (int mi = 0; mi < 4; mi++)
#pragma unroll
            for (int nj = 0; nj < 4; nj++)
#pragma unroll
                for (int r = 0; r < 4; r++) acc[mi][nj][r] = 0.f;

        load_stage(sbase, 0, 0, t, row0, gr, sh, bh);
        CP_COMMIT();
        load_stage(sbase, STAGE_B, 1, t, row0, gr, sh, bh);
        CP_COMMIT();

        for (int kt = 0; kt < 16; kt++) {
            unsigned buf = (unsigned)((kt % 3) * STAGE_B);
            if (kt + 2 < 16) {
                unsigned nslot = (unsigned)(((kt + 2) % 3) * STAGE_B);
                load_stage(sbase, nslot, kt + 2, t, row0, gr, sh, bh);
                CP_COMMIT();
                CP_WAIT2();
            } else if (kt + 1 < 16) {
                CP_WAIT1();
            } else {
                CP_WAIT0();
            }
            __syncthreads();

            unsigned A = sbase + buf;
            unsigned B = A + TILE_B;
#pragma unroll
            for (int k16 = 0; k16 < 2; k16++) {
                unsigned kb = (unsigned)(k16 * 32);
                unsigned a[4][4], bb[2][4];
#pragma unroll
                for (int mi = 0; mi < 4; mi++)
                    ldsm4(a[mi], A + a_off + mi * 1280 + kb);
#pragma unroll
                for (int np = 0; np < 2; np++)
                    ldsm4(bb[np], B + b_off + np * 1280 + kb);
#pragma unroll
                for (int mi = 0; mi < 4; mi++)
#pragma unroll
                    for (int nj = 0; nj < 4; nj++)
                        mma16816(acc[mi][nj], a[mi][0], a[mi][1], a[mi][2], a[mi][3],
                                 bb[nj >> 1][(nj & 1) * 2], bb[nj >> 1][(nj & 1) * 2 + 1]);
            }
            __syncthreads();
        }

#pragma unroll
        for (int mi = 0; mi < 4; mi++)
#pragma unroll
            for (int nj = 0; nj < 4; nj++) {
                int c0 = ht * 128 + wn * 32 + nj * 8 + qc * 2;
                float d0 = DV[c0], d1 = DV[c0 + 1];
                float v0 = VV[c0], v1 = VV[c0 + 1];
                sacc[mi][0] += v0 * tanhf(acc[mi][nj][0] + d0)
                             + v1 * tanhf(acc[mi][nj][1] + d1);
                sacc[mi][1] += v0 * tanhf(acc[mi][nj][2] + d0)
                             + v1 * tanhf(acc[mi][nj][3] + d1);
            }
    }

#pragma unroll
    for (int mi = 0; mi < 4; mi++) {
#pragma unroll
        for (int h = 0; h < 2; h++) {
            float s = sacc[mi][h];
            s += __shfl_xor_sync(0xffffffffu, s, 1);
            s += __shfl_xor_sync(0xffffffffu, s, 2);
            sacc[mi][h] = s;
        }
    }
    if (qc == 0) {
#pragma unroll
        for (int mi = 0; mi < 4; mi++) {
            int r = wm * 64 + mi * 16 + qr;
            RED[wn * 128 + r]     = sacc[mi][0];
            RED[wn * 128 + r + 8] = sacc[mi][1];
        }
    }
    __syncthreads();
    if (t < 128) {
        float s = RED[t] + RED[128 + t] + RED[256 + t] + RED[384 + t];
        (g ? sc_t : sc_e)[row0 + t] = s;
    }
}

// ===========================================================================
// ptr GEMM with fused final pointer-score epilogue.  grid (512).
// out[row] = 5 * sum_h v[h]*tanh(S+cptr+ss) + sum_h v[h]*tanh(S+ctptr+ss)
// ===========================================================================
__global__ void __launch_bounds__(256, 2)
big_mma_ptr_k(const __half* __restrict__ sh, const __half* __restrict__ bh,
              const float* __restrict__ cptr, const float* __restrict__ ctptr,
              const float* __restrict__ ss, const float* __restrict__ vp,
              float* __restrict__ out)
{
    extern __shared__ __align__(128) unsigned char smem[];
    unsigned sbase = smem_u32(smem);
    int t = threadIdx.x;
    int lane = t & 31, wid = t >> 5;
    int wm = wid & 1, wn = wid >> 1;
    int qr = lane >> 2, qc = lane & 3;
    int row0 = blockIdx.x * 128;
    int b = blockIdx.x >> 2;

    int lrow = lane & 7, lsel = lane >> 3;
    unsigned a_off = (unsigned)((wm * 64 + (lsel & 1) * 8 + lrow) * 80 + (lsel >> 1) * 16);
    unsigned b_off = (unsigned)((wn * 32 + (lsel >> 1) * 8 + lrow) * 80 + (lsel & 1) * 16);

    float* A1  = (float*)(smem + SM_A1);
    float* A2  = (float*)(smem + SM_A2);
    float* PV  = (float*)(smem + SM_PV);
    float* RED = (float*)(smem + SM_RED2);     // [4][256]: (s1,s2) per row
    for (int i = t; i < 512; i += 256) {
        float s0 = ss[b * 512 + i];
        A1[i] = cptr[b * 512 + i] + s0;
        A2[i] = ctptr[b * 512 + i] + s0;
        PV[i] = vp[i];
    }

    float s1a[4][2], s2a[4][2];
#pragma unroll
    for (int i = 0; i < 4; i++) {
        s1a[i][0] = 0.f; s1a[i][1] = 0.f;
        s2a[i][0] = 0.f; s2a[i][1] = 0.f;
    }

    for (int ht = 0; ht < 4; ht++) {
        int gr = 1024 + ht * 128;              // ptr rows in Bcat
        float acc[4][4][4];
#pragma unroll
        for (int mi = 0; mi < 4; mi++)
#pragma unroll
            for (int nj = 0; nj < 4; nj++)
#pragma unroll
                for (int r = 0; r < 4; r++) acc[mi][nj][r] = 0.f;

        load_stage(sbase, 0, 0, t, row0, gr, sh, bh);
        CP_COMMIT();
        load_stage(sbase, STAGE_B, 1, t, row0, gr, sh, bh);
        CP_COMMIT();

        for (int kt = 0; kt < 16; kt++) {
            unsigned buf = (unsigned)((kt % 3) * STAGE_B);
            if (kt + 2 < 16) {
                unsigned nslot = (unsigned)(((kt + 2) % 3) * STAGE_B);
                load_stage(sbase, nslot, kt + 2, t, row0, gr, sh, bh);
                CP_COMMIT();
                CP_WAIT2();
            } else if (kt + 1 < 16) {
                CP_WAIT1();
            } else {
                CP_WAIT0();
            }
            __syncthreads();

            unsigned A = sbase + buf;
            unsigned B = A + TILE_B;
#pragma unroll
            for (int k16 = 0; k16 < 2; k16++) {
                unsigned kb = (unsigned)(k16 * 32);
                unsigned a[4][4], bb[2][4];
#pragma unroll
                for (int mi = 0; mi < 4; mi++)
                    ldsm4(a[mi], A + a_off + mi * 1280 + kb);
#pragma unroll
                for (int np = 0; np < 2; np++)
                    ldsm4(bb[np], B + b_off + np * 1280 + kb);
#pragma unroll
                for (int mi = 0; mi < 4; mi++)
#pragma unroll
                    for (int nj = 0; nj < 4; nj++)
                        mma16816(acc[mi][nj], a[mi][0], a[mi][1], a[mi][2], a[mi][3],
                                 bb[nj >> 1][(nj & 1) * 2], bb[nj >> 1][(nj & 1) * 2 + 1]);
            }
            __syncthreads();
        }

        // fused pointer-score epilogue for this ht block
#pragma unroll
        for (int mi = 0; mi < 4; mi++)
#pragma unroll
            for (int nj = 0; nj < 4; nj++) {
                int c0 = ht * 128 + wn * 32 + nj * 8 + qc * 2;
                float a10 = A1[c0], a11 = A1[c0 + 1];
                float a20 = A2[c0], a21 = A2[c0 + 1];
                float v0 = PV[c0], v1 = PV[c0 + 1];
                float x0 = acc[mi][nj][0], x1 = acc[mi][nj][1];
                float x2 = acc[mi][nj][2], x3 = acc[mi][nj][3];
                s1a[mi][0] += v0 * tanhf(x0 + a10) + v1 * tanhf(x1 + a11);
                s2a[mi][0] += v0 * tanhf(x0 + a20) + v1 * tanhf(x1 + a21);
                s1a[mi][1] += v0 * tanhf(x2 + a10) + v1 * tanhf(x3 + a11);
                s2a[mi][1] += v0 * tanhf(x2 + a20) + v1 * tanhf(x3 + a21);
            }
    }

#pragma unroll
    for (int mi = 0; mi < 4; mi++) {
#pragma unroll
        for (int h = 0; h < 2; h++) {
            float s1 = s1a[mi][h], s2 = s2a[mi][h];
            s1 += __shfl_xor_sync(0xffffffffu, s1, 1);
            s1 += __shfl_xor_sync(0xffffffffu, s1, 2);
            s2 += __shfl_xor_sync(0xffffffffu, s2, 1);
            s2 += __shfl_xor_sync(0xffffffffu, s2, 2);
            s1a[mi][h] = s1; s2a[mi][h] = s2;
        }
    }
    if (qc == 0) {
#pragma unroll
        for (int mi = 0; mi < 4; mi++) {
            int r = wm * 64 + mi * 16 + qr;
            RED[wn * 256 + r * 2]            = s1a[mi][0];
            RED[wn * 256 + r * 2 + 1]        = s2a[mi][0];
            RED[wn * 256 + (r + 8) * 2]      = s1a[mi][1];
            RED[wn * 256 + (r + 8) * 2 + 1]  = s2a[mi][1];
        }
    }
    __syncthreads();
    if (t < 128) {
        float s1 = RED[t * 2]     + RED[256 + t * 2]     + RED[512 + t * 2]     + RED[768 + t * 2];
        float s2 = RED[t * 2 + 1] + RED[256 + t * 2 + 1] + RED[512 + t * 2 + 1] + RED[768 + t * 2 + 1];
        out[row0 + t] = 5.0f * s1 + s2;
    }
}

// ===========================================================================
__global__ void softmax_k(const float* __restrict__ score_e, const float* __restrict__ score_t,
                          float* __restrict__ attn_e, float* __restrict__ attn_t)
{
    int b = blockIdx.x & 127;
    int wh = blockIdx.x >> 7;
    const float* src = (wh ? score_t : score_e) + b * 512;
    float* dst = (wh ? attn_t : attn_e) + b * 512;
    int t = threadIdx.x;
    float v0 = src[t], v1 = src[t + 256];
    __shared__ float red[256];
    red[t] = fmaxf(v0, v1);
    __syncthreads();
    for (int s = 128; s > 0; s >>= 1) {
        if (t < s) red[t] = fmaxf(red[t], red[t + s]);
        __syncthreads();
    }
    float mx = red[0];
    __syncthreads();
    float e0 = expf(v0 - mx), e1 = expf(v1 - mx);
    red[t] = e0 + e1;
    __syncthreads();
    for (int s = 128; s > 0; s >>= 1) {
        if (t < s) red[t] += red[t + s];
        __syncthreads();
    }
    float inv = 1.f / red[0];
    dst[t] = e0 * inv;
    dst[t + 256] = e1 * inv;
}

// contexts from the fp16 copy of static_hidden (half the traffic)
__global__ void context_k(const __half* __restrict__ sh,
                          const float* __restrict__ ae, const float* __restrict__ at,
                          float* __restrict__ ce, float* __restrict__ ct)
{
    int b = blockIdx.x >> 2;
    int ch = blockIdx.x & 3;
    int h = ch * 128 + threadIdx.x;
    __shared__ float sae[512], sat[512];
    for (int i = threadIdx.x; i < 512; i += 128) {
        sae[i] = ae[b * 512 + i];
        sat[i] = at[b * 512 + i];
    }
    __syncthreads();
    const __half* Sb = sh + (size_t)b * 262144 + h;
    float se = 0.f, st = 0.f;
#pragma unroll 8
    for (int n = 0; n < 512; n++) {
        float sv = __half2float(Sb[(size_t)n * 512]);
        se += sae[n] * sv;
        st += sat[n] * sv;
    }
    ce[b * 512 + h] = se;
    ct[b * 512 + h] = st;
}

// ===========================================================================
extern "C" void kernel_launch(void* const* d_in, const int* in_sizes, int n_in,
                              void* d_out, int out_size)
{
    const float* stat = (const float*)d_in[0];   // (128,512,512)
    const float* semb = (const float*)d_in[1];   // (128,1,512)
    const float* dech = (const float*)d_in[2];   // (128,1,512)
    const float* tgth = (const float*)d_in[3];   // (128,1,512)
    const float* lhh  = (const float*)d_in[4];   // (1,128,512)
    const float* ptrv = (const float*)d_in[5];   // (1,1,512)
    const float* ptrW = (const float*)d_in[6];   // (1,512,1536)
    const float* encv = (const float*)d_in[7];   // (1,1,512)
    const float* encW = (const float*)d_in[8];   // (1,512,1024)
    const float* tgtv = (const float*)d_in[9];   // (1,1,512)
    const float* tgtW = (const float*)d_in[10];  // (1,512,1024)
    const float* wih  = (const float*)d_in[11];  // (1536,512)
    const float* whh  = (const float*)d_in[12];  // (1536,512)
    const float* bih  = (const float*)d_in[13];
    const float* bhh  = (const float*)d_in[14];
    float* out = (float*)d_out;

    unsigned char* base = nullptr;
    cudaGetSymbolAddress((void**)&base, g_scratch);
    __half* sh = (__half*)(base + OFF_SH);
    __half* bhp = (__half*)(base + OFF_BH);
    float* FL = (float*)(base + OFF_FL);
    float* gx     = FL + FO_GX;
    float* gh     = FL + FO_GH;
    float* hnew   = FL + FO_HNEW;
    float* denc   = FL + FO_DENC;
    float* dtgt   = FL + FO_DTGT;
    float* sstate = FL + FO_SSTATE;
    float* cptr   = FL + FO_CPTR;
    float* ctptr  = FL + FO_CTPTR;
    float* ctxe   = FL + FO_CTXE;
    float* ctxt   = FL + FO_CTXT;
    float* sc_e   = FL + FO_SCE;
    float* sc_t   = FL + FO_SCT;
    float* at_e   = FL + FO_ATE;
    float* at_t   = FL + FO_ATT;

    // Attribute cache: set once on the (uncaptured) correctness call.
    static bool attr_done = false;
    if (!attr_done) {
        cudaFuncSetAttribute(big_mma_et_k, cudaFuncAttributeMaxDynamicSharedMemorySize,
                             SMEM_ET);
        cudaFuncSetAttribute(big_mma_ptr_k, cudaFuncAttributeMaxDynamicSharedMemorySize,
                             SMEM_PTR);
        attr_done = true;
    }

    // conversions
    convert_w_k<<<768, 256>>>(encW, tgtW, ptrW, (__half2*)bhp);
    convert_stat_k<<<32768, 256>>>(stat, (__half2*)sh);

    // GRU input/hidden GEMMs (z-batched)
    small_gemm3_k<<<dim3(24, 4, 2), 256>>>(
        dech, wih, 512, 0, gx, 1536,
        lhh,  whh, 512, 0, gh, 1536,
        lhh,  whh, 512, 0, gh, 1536);
    gru_gates_k<<<256, 256>>>(gx, gh, bih, bhh, lhh, hnew, out + 65536);

    // per-batch bias projections (z-batched)
    small_gemm3_k<<<dim3(8, 4, 3), 256>>>(
        hnew, encW, 1024, 512,  denc,   512,
        tgth, tgtW, 1024, 512,  dtgt,   512,
        semb, ptrW, 1536, 1024, sstate, 512);

    // enc/tgt GEMM -> scores
    big_mma_et_k<<<dim3(2, 512), 256, SMEM_ET>>>(sh, bhp, denc, dtgt,
                                                 encv, tgtv, sc_e, sc_t);

    // softmax + contexts + context projections
    softmax_k<<<256, 256>>>(sc_e, sc_t, at_e, at_t);
    context_k<<<512, 128>>>(sh, at_e, at_t, ctxe, ctxt);
    small_gemm3_k<<<dim3(8, 4, 2), 256>>>(
        ctxe, ptrW, 1536, 512, cptr,  512,
        ctxt, ptrW, 1536, 512, ctptr, 512,
        ctxt, ptrW, 1536, 512, ctptr, 512);

    // ptr GEMM with fused final pointer-score epilogue -> probs
    big_mma_ptr_k<<<512, 256, SMEM_PTR>>>(sh, bhp, cptr, ctptr, sstate, ptrv, out);
}

// round 14
// speedup vs baseline: 4.3016x; 1.0388x over previous
#include <cuda_runtime.h>
#include <cuda_fp16.h>

// ===========================================================================
// B=128, N=512, H=512.  Output: [probs 65536 | new_last_hh 65536] fp32
// fp16 mma.sync + ldmatrix big GEMM (legacy-HMMA-rate bound), fused epilogues.
// R13 with the SMEM-alignment bug fixed (scalar tile stores, stride 65).
// ===========================================================================

// -------------------- scratch (byte offsets) --------------------------------
#define OFF_SH     0L                       // stat fp16 [65536][512]
#define OFF_BH     67108864L                // Bcat fp16 [1536][512]
#define OFF_FL     68681728L                // float region
#define SCRATCH_BYTES (OFF_FL + 4718592L)
__device__ __align__(1024) unsigned char g_scratch[SCRATCH_BYTES];

// float sub-offsets (in floats) inside FL region
#define FO_GX     0L
#define FO_GH     196608L
#define FO_HNEW   393216L
#define FO_DENC   458752L
#define FO_DTGT   524288L
#define FO_SSTATE 589824L
#define FO_CPTR   655360L
#define FO_CTPTR  720896L
#define FO_CTXE   786432L
#define FO_CTXT   851968L
#define FO_SCE    917504L
#define FO_SCT    983040L
#define FO_ATE    1048576L
#define FO_ATT    1114112L

// ===================== PTX helpers (baseline ISA only) ======================
__device__ __forceinline__ unsigned smem_u32(const void* p) {
    unsigned a;
    asm("{ .reg .u64 t; cvta.to.shared.u64 t, %1; cvt.u32.u64 %0, t; }"
        : "=r"(a) : "l"(p));
    return a;
}
__device__ __forceinline__ void cp16(unsigned dst, const void* src) {
    asm volatile("cp.async.cg.shared.global [%0], [%1], 16;" :: "r"(dst), "l"(src));
}
#define CP_COMMIT() asm volatile("cp.async.commit_group;" ::: "memory")
#define CP_WAIT2()  asm volatile("cp.async.wait_group 2;" ::: "memory")
#define CP_WAIT1()  asm volatile("cp.async.wait_group 1;" ::: "memory")
#define CP_WAIT0()  asm volatile("cp.async.wait_group 0;" ::: "memory")

__device__ __forceinline__ void mma16816(float c[4],
        unsigned a0, unsigned a1, unsigned a2, unsigned a3,
        unsigned b0, unsigned b1) {
    asm volatile(
        "mma.sync.aligned.m16n8k16.row.col.f32.f16.f16.f32 "
        "{%0,%1,%2,%3}, {%4,%5,%6,%7}, {%8,%9}, {%0,%1,%2,%3};"
        : "+f"(c[0]), "+f"(c[1]), "+f"(c[2]), "+f"(c[3])
        : "r"(a0), "r"(a1), "r"(a2), "r"(a3), "r"(b0), "r"(b1));
}
__device__ __forceinline__ void ldsm4(unsigned r[4], unsigned addr) {
    asm volatile("ldmatrix.sync.aligned.m8n8.x4.shared.b16 {%0,%1,%2,%3}, [%4];"
        : "=r"(r[0]), "=r"(r[1]), "=r"(r[2]), "=r"(r[3]) : "r"(addr));
}

// tanh(x) = 1 - 2/(e^{2x}+1) with MUFU ex2/rcp (rel err ~1e-7, ~6 instr).
__device__ __forceinline__ float fast_tanh(float x) {
    float e, r;
    asm("ex2.approx.f32 %0, %1;" : "=f"(e) : "f"(x * 2.8853900817779268f));
    asm("rcp.approx.f32 %0, %1;" : "=f"(r) : "f"(e + 1.0f));
    return 1.0f - 2.0f * r;
}

// ===========================================================================
// fp32 -> fp16 conversions
// ===========================================================================
__global__ void __launch_bounds__(256)
convert_stat_k(const float* __restrict__ x, __half2* __restrict__ h)
{
    size_t i = (size_t)blockIdx.x * 256 + threadIdx.x;   // 8388608 quads
    float4 v = ((const float4*)x)[i];
    h[2 * i]     = __floats2half2_rn(v.x, v.y);
    h[2 * i + 1] = __floats2half2_rn(v.z, v.w);
}

// Bcat[1536][512]: rows 0-511 encW static, 512-1023 tgtW static, 1024-1535 ptrW static
__global__ void __launch_bounds__(256)
convert_w_k(const float* __restrict__ encW, const float* __restrict__ tgtW,
            const float* __restrict__ ptrW, __half2* __restrict__ h)
{
    int i = blockIdx.x * 256 + threadIdx.x;              // 196608 quads
    int e = i * 4;
    int row = e >> 9, k = e & 511;
    const float* src;
    if (row < 512)       src = encW + (size_t)row * 1024 + k;
    else if (row < 1024) src = tgtW + (size_t)(row - 512) * 1024 + k;
    else                 src = ptrW + (size_t)(row - 1024) * 1536 + k;
    float4 v = *(const float4*)src;
    h[2 * i]     = __floats2half2_rn(v.x, v.y);
    h[2 * i + 1] = __floats2half2_rn(v.z, v.w);
}

// ===========================================================================
// Small GEMM, z-batched, register-prefetched: C[128 x N] = A[128x512] @ W^T
// tile 32 rows x 64 cols, K-chunk 64 (8 iterations), 256 threads.
// SMEM stores are SCALAR (stride-65 rows are not 16B aligned).
// ===========================================================================
__global__ void __launch_bounds__(256)
small_gemm3_k(const float* A0, const float* W0, int ldw0, int wofs0, float* C0, int ldc0,
              const float* A1, const float* W1, int ldw1, int wofs1, float* C1, int ldc1,
              const float* A2, const float* W2, int ldw2, int wofs2, float* C2, int ldc2)
{
    int z = blockIdx.z;
    const float* A = (z == 0) ? A0 : (z == 1) ? A1 : A2;
    const float* W = (z == 0) ? W0 : (z == 1) ? W1 : W2;
    int ldw  = (z == 0) ? ldw0  : (z == 1) ? ldw1  : ldw2;
    int wofs = (z == 0) ? wofs0 : (z == 1) ? wofs1 : wofs2;
    float* C = (z == 0) ? C0 : (z == 1) ? C1 : C2;
    int ldc  = (z == 0) ? ldc0 : (z == 1) ? ldc1 : ldc2;

    __shared__ float As[32][65];
    __shared__ float Ws[64][65];
    int t = threadIdx.x;
    int c = t & 63, rg = t >> 6;
    int row0 = blockIdx.y * 32, col0 = blockIdx.x * 64;

    int arow = t >> 3, ak = (t & 7) * 8;     // A: 32 rows x 64 k, 8 floats/thread
    int wrow = t >> 2, wk = (t & 3) * 16;    // W: 64 rows x 64 k, 16 floats/thread
    const float* Ap = A + (size_t)(row0 + arow) * 512 + ak;
    const float* Wp = W + (size_t)(col0 + wrow) * ldw + wofs + wk;

    float acc[8];
#pragma unroll
    for (int i = 0; i < 8; i++) acc[i] = 0.f;

    float4 a0 = *(const float4*)(Ap);
    float4 a1 = *(const float4*)(Ap + 4);
    float4 w0 = *(const float4*)(Wp);
    float4 w1 = *(const float4*)(Wp + 4);
    float4 w2 = *(const float4*)(Wp + 8);
    float4 w3 = *(const float4*)(Wp + 12);

    for (int k0 = 0; k0 < 512; k0 += 64) {
        // scalar stores (alignment-safe for odd row stride)
        As[arow][ak]     = a0.x; As[arow][ak + 1] = a0.y;
        As[arow][ak + 2] = a0.z; As[arow][ak + 3] = a0.w;
        As[arow][ak + 4] = a1.x; As[arow][ak + 5] = a1.y;
        As[arow][ak + 6] = a1.z; As[arow][ak + 7] = a1.w;
        Ws[wrow][wk]      = w0.x; Ws[wrow][wk + 1]  = w0.y;
        Ws[wrow][wk + 2]  = w0.z; Ws[wrow][wk + 3]  = w0.w;
        Ws[wrow][wk + 4]  = w1.x; Ws[wrow][wk + 5]  = w1.y;
        Ws[wrow][wk + 6]  = w1.z; Ws[wrow][wk + 7]  = w1.w;
        Ws[wrow][wk + 8]  = w2.x; Ws[wrow][wk + 9]  = w2.y;
        Ws[wrow][wk + 10] = w2.z; Ws[wrow][wk + 11] = w2.w;
        Ws[wrow][wk + 12] = w3.x; Ws[wrow][wk + 13] = w3.y;
        Ws[wrow][wk + 14] = w3.z; Ws[wrow][wk + 15] = w3.w;
        __syncthreads();
        if (k0 + 64 < 512) {
            a0 = *(const float4*)(Ap + k0 + 64);
            a1 = *(const float4*)(Ap + k0 + 68);
            w0 = *(const float4*)(Wp + k0 + 64);
            w1 = *(const float4*)(Wp + k0 + 68);
            w2 = *(const float4*)(Wp + k0 + 72);
            w3 = *(const float4*)(Wp + k0 + 76);
        }
#pragma unroll
        for (int kk = 0; kk < 64; kk++) {
            float wv = Ws[c][kk];
#pragma unroll
            for (int i = 0; i < 8; i++)
                acc[i] += As[rg * 8 + i][kk] * wv;
        }
        __syncthreads();
    }
#pragma unroll
    for (int i = 0; i < 8; i++)
        C[(size_t)(row0 + rg * 8 + i) * ldc + col0 + c] = acc[i];
}

// ===========================================================================
__global__ void gru_gates_k(const float* __restrict__ gx, const float* __restrict__ gh,
                            const float* __restrict__ bih, const float* __restrict__ bhh,
                            const float* __restrict__ lhh,
                            float* __restrict__ hnew, float* __restrict__ outh)
{
    int i = blockIdx.x * blockDim.x + threadIdx.x;
    int b = i >> 9, j = i & 511;
    const float* gxb = gx + b * 1536;
    const float* ghb = gh + b * 1536;
    float xr = gxb[j] + bih[j],              hr = ghb[j] + bhh[j];
    float xz = gxb[512 + j] + bih[512 + j],  hz = ghb[512 + j] + bhh[512 + j];
    float xn = gxb[1024 + j] + bih[1024 + j];
    float hn = ghb[1024 + j] + bhh[1024 + j];
    float r = 1.f / (1.f + expf(-(xr + hr)));
    float z = 1.f / (1.f + expf(-(xz + hz)));
    float n = tanhf(xn + r * hn);
    float h = lhh[i];
    float v = (1.f - z) * n + z * h;
    hnew[i] = v;
    outh[i] = v;
}

// ===========================================================================
// Shared mainloop constants.
// SMEM: [0,61440) 3 stages x (A tile + B tile), tile = 128 rows x 80B (64B data)
// ===========================================================================
#define TILE_B   10240
#define STAGE_B  20480
// et kernel extras
#define SM_DV    61440
#define SM_VV    63488
#define SM_RED   65536
#define SMEM_ET  67584
// ptr kernel extras
#define SM_A1    61440
#define SM_A2    63488
#define SM_PV    65536
#define SM_RED2  67584
#define SMEM_PTR 71680

__device__ __forceinline__ void load_stage(
    unsigned sbase, unsigned bufbase, int kt, int t, int row0, int grow,
    const __half* __restrict__ sh, const __half* __restrict__ bh)
{
    int tsel = t >> 7;           // 0:A 1:B
    int tt = t & 127;
    const __half* base = tsel ? bh : sh;
    int roff = tsel ? grow : row0;
    unsigned stile = sbase + bufbase + (unsigned)(tsel * TILE_B) + (unsigned)(tt * 80);
    const __half* src = base + (size_t)(roff + tt) * 512 + kt * 32;
#pragma unroll
    for (int c = 0; c < 4; c++)
        cp16(stile + (unsigned)(c * 16), src + c * 8);
}

// ===========================================================================
// enc/tgt GEMM + score epilogue.  grid (2, 512): g = {enc, tgt}
// ===========================================================================
__global__ void __launch_bounds__(256, 2)
big_mma_et_k(const __half* __restrict__ sh, const __half* __restrict__ bh,
             const float* __restrict__ denc, const float* __restrict__ dtgt,
             const float* __restrict__ encv, const float* __restrict__ tgtv,
             float* __restrict__ sc_e, float* __restrict__ sc_t)
{
    extern __shared__ __align__(128) unsigned char smem[];
    unsigned sbase = smem_u32(smem);
    int t = threadIdx.x;
    int lane = t & 31, wid = t >> 5;
    int wm = wid & 1, wn = wid >> 1;
    int qr = lane >> 2, qc = lane & 3;
    int g = blockIdx.x;
    int row0 = blockIdx.y * 128;
    int b = blockIdx.y >> 2;
    int grow = g * 512;

    int lrow = lane & 7, lsel = lane >> 3;
    unsigned a_off = (unsigned)((wm * 64 + (lsel & 1) * 8 + lrow) * 80 + (lsel >> 1) * 16);
    unsigned b_off = (unsigned)((wn * 32 + (lsel >> 1) * 8 + lrow) * 80 + (lsel & 1) * 16);

    float* DV  = (float*)(smem + SM_DV);
    float* VV  = (float*)(smem + SM_VV);
    float* RED = (float*)(smem + SM_RED);
    {
        const float* dsrc = g ? dtgt : denc;
        const float* vsrc = g ? tgtv : encv;
        for (int i = t; i < 512; i += 256) { DV[i] = dsrc[b * 512 + i]; VV[i] = vsrc[i]; }
    }

    float sacc[4][2];
#pragma unroll
    for (int i = 0; i < 4; i++) { sacc[i][0] = 0.f; sacc[i][1] = 0.f; }

    for (int ht = 0; ht < 4; ht++) {
        int gr = grow + ht * 128;
        float acc[4][4][4];
#pragma unroll
        for (int mi = 0; mi < 4; mi++)
#pragma unroll
            for (int nj = 0; nj < 4; nj++)
#pragma unroll
                for (int r = 0; r < 4; r++) acc[mi][nj][r] = 0.f;

        load_stage(sbase, 0, 0, t, row0, gr, sh, bh);
        CP_COMMIT();
        load_stage(sbase, STAGE_B, 1, t, row0, gr, sh, bh);
        CP_COMMIT();

        for (int kt = 0; kt < 16; kt++) {
            unsigned buf = (unsigned)((kt % 3) * STAGE_B);
            if (kt + 2 < 16) {
                unsigned nslot = (unsigned)(((kt + 2) % 3) * STAGE_B);
                load_stage(sbase, nslot, kt + 2, t, row0, gr, sh, bh);
                CP_COMMIT();
                CP_WAIT2();
            } else if (kt + 1 < 16) {
                CP_WAIT1();
            } else {
                CP_WAIT0();
            }
            __syncthreads();

            unsigned A = sbase + buf;
            unsigned B = A + TILE_B;
#pragma unroll
            for (int k16 = 0; k16 < 2; k16++) {
                unsigned kb = (unsigned)(k16 * 32);
                unsigned a[4][4], bb[2][4];
#pragma unroll
                for (int mi = 0; mi < 4; mi++)
                    ldsm4(a[mi], A + a_off + mi * 1280 + kb);
#pragma unroll
                for (int np = 0; np < 2; np++)
                    ldsm4(bb[np], B + b_off + np * 1280 + kb);
#pragma unroll
                for (int mi = 0; mi < 4; mi++)
#pragma unroll
                    for (int nj = 0; nj < 4; nj++)
                        mma16816(acc[mi][nj], a[mi][0], a[mi][1], a[mi][2], a[mi][3],
                                 bb[nj >> 1][(nj & 1) * 2], bb[nj >> 1][(nj & 1) * 2 + 1]);
            }
            __syncthreads();
        }

#pragma unroll
        for (int mi = 0; mi < 4; mi++)
#pragma unroll
            for (int nj = 0; nj < 4; nj++) {
                int c0 = ht * 128 + wn * 32 + nj * 8 + qc * 2;
                float d0 = DV[c0], d1 = DV[c0 + 1];
                float v0 = VV[c0], v1 = VV[c0 + 1];
                sacc[mi][0] += v0 * fast_tanh(acc[mi][nj][0] + d0)
                             + v1 * fast_tanh(acc[mi][nj][1] + d1);
                sacc[mi][1] += v0 * fast_tanh(acc[mi][nj][2] + d0)
                             + v1 * fast_tanh(acc[mi][nj][3] + d1);
            }
    }

#pragma unroll
    for (int mi = 0; mi < 4; mi++) {
#pragma unroll
        for (int h = 0; h < 2; h++) {
            float s = sacc[mi][h];
            s += __shfl_xor_sync(0xffffffffu, s, 1);
            s += __shfl_xor_sync(0xffffffffu, s, 2);
            sacc[mi][h] = s;
        }
    }
    if (qc == 0) {
#pragma unroll
        for (int mi = 0; mi < 4; mi++) {
            int r = wm * 64 + mi * 16 + qr;
            RED[wn * 128 + r]     = sacc[mi][0];
            RED[wn * 128 + r + 8] = sacc[mi][1];
        }
    }
    __syncthreads();
    if (t < 128) {
        float s = RED[t] + RED[128 + t] + RED[256 + t] + RED[384 + t];
        (g ? sc_t : sc_e)[row0 + t] = s;
    }
}

// ===========================================================================
// ptr GEMM with fused final pointer-score epilogue.  grid (512).
// ===========================================================================
__global__ void __launch_bounds__(256, 2)
big_mma_ptr_k(const __half* __restrict__ sh, const __half* __restrict__ bh,
              const float* __restrict__ cptr, const float* __restrict__ ctptr,
              const float* __restrict__ ss, const float* __restrict__ vp,
              float* __restrict__ out)
{
    extern __shared__ __align__(128) unsigned char smem[];
    unsigned sbase = smem_u32(smem);
    int t = threadIdx.x;
    int lane = t & 31, wid = t >> 5;
    int wm = wid & 1, wn = wid >> 1;
    int qr = lane >> 2, qc = lane & 3;
    int row0 = blockIdx.x * 128;
    int b = blockIdx.x >> 2;

    int lrow = lane & 7, lsel = lane >> 3;
    unsigned a_off = (unsigned)((wm * 64 + (lsel & 1) * 8 + lrow) * 80 + (lsel >> 1) * 16);
    unsigned b_off = (unsigned)((wn * 32 + (lsel >> 1) * 8 + lrow) * 80 + (lsel & 1) * 16);

    float* A1  = (float*)(smem + SM_A1);
    float* A2  = (float*)(smem + SM_A2);
    float* PV  = (float*)(smem + SM_PV);
    float* RED = (float*)(smem + SM_RED2);
    for (int i = t; i < 512; i += 256) {
        float s0 = ss[b * 512 + i];
        A1[i] = cptr[b * 512 + i] + s0;
        A2[i] = ctptr[b * 512 + i] + s0;
        PV[i] = vp[i];
    }

    float s1a[4][2], s2a[4][2];
#pragma unroll
    for (int i = 0; i < 4; i++) {
        s1a[i][0] = 0.f; s1a[i][1] = 0.f;
        s2a[i][0] = 0.f; s2a[i][1] = 0.f;
    }

    for (int ht = 0; ht < 4; ht++) {
        int gr = 1024 + ht * 128;
        float acc[4][4][4];
#pragma unroll
        for (int mi = 0; mi < 4; mi++)
#pragma unroll
            for (int nj = 0; nj < 4; nj++)
#pragma unroll
                for (int r = 0; r < 4; r++) acc[mi][nj][r] = 0.f;

        load_stage(sbase, 0, 0, t, row0, gr, sh, bh);
        CP_COMMIT();
        load_stage(sbase, STAGE_B, 1, t, row0, gr, sh, bh);
        CP_COMMIT();

        for (int kt = 0; kt < 16; kt++) {
            unsigned buf = (unsigned)((kt % 3) * STAGE_B);
            if (kt + 2 < 16) {
                unsigned nslot = (unsigned)(((kt + 2) % 3) * STAGE_B);
                load_stage(sbase, nslot, kt + 2, t, row0, gr, sh, bh);
                CP_COMMIT();
                CP_WAIT2();
            } else if (kt + 1 < 16) {
                CP_WAIT1();
            } else {
                CP_WAIT0();
            }
            __syncthreads();

            unsigned A = sbase + buf;
            unsigned B = A + TILE_B;
#pragma unroll
            for (int k16 = 0; k16 < 2; k16++) {
                unsigned kb = (unsigned)(k16 * 32);
                unsigned a[4][4], bb[2][4];
#pragma unroll
                for (int mi = 0; mi < 4; mi++)
                    ldsm4(a[mi], A + a_off + mi * 1280 + kb);
#pragma unroll
                for (int np = 0; np < 2; np++)
                    ldsm4(bb[np], B + b_off + np * 1280 + kb);
#pragma unroll
                for (int mi = 0; mi < 4; mi++)
#pragma unroll
                    for (int nj = 0; nj < 4; nj++)
                        mma16816(acc[mi][nj], a[mi][0], a[mi][1], a[mi][2], a[mi][3],
                                 bb[nj >> 1][(nj & 1) * 2], bb[nj >> 1][(nj & 1) * 2 + 1]);
            }
            __syncthreads();
        }

        // fused pointer-score epilogue for this ht block
#pragma unroll
        for (int mi = 0; mi < 4; mi++)
#pragma unroll
            for (int nj = 0; nj < 4; nj++) {
                int c0 = ht * 128 + wn * 32 + nj * 8 + qc * 2;
                float a10 = A1[c0], a11 = A1[c0 + 1];
                float a20 = A2[c0], a21 = A2[c0 + 1];
                float v0 = PV[c0], v1 = PV[c0 + 1];
                float x0 = acc[mi][nj][0], x1 = acc[mi][nj][1];
                float x2 = acc[mi][nj][2], x3 = acc[mi][nj][3];
                s1a[mi][0] += v0 * fast_tanh(x0 + a10) + v1 * fast_tanh(x1 + a11);
                s2a[mi][0] += v0 * fast_tanh(x0 + a20) + v1 * fast_tanh(x1 + a21);
                s1a[mi][1] += v0 * fast_tanh(x2 + a10) + v1 * fast_tanh(x3 + a11);
                s2a[mi][1] += v0 * fast_tanh(x2 + a20) + v1 * fast_tanh(x3 + a21);
            }
    }

#pragma unroll
    for (int mi = 0; mi < 4; mi++) {
#pragma unroll
        for (int h = 0; h < 2; h++) {
            float s1 = s1a[mi][h], s2 = s2a[mi][h];
            s1 += __shfl_xor_sync(0xffffffffu, s1, 1);
            s1 += __shfl_xor_sync(0xffffffffu, s1, 2);
            s2 += __shfl_xor_sync(0xffffffffu, s2, 1);
            s2 += __shfl_xor_sync(0xffffffffu, s2, 2);
            s1a[mi][h] = s1; s2a[mi][h] = s2;
        }
    }
    if (qc == 0) {
#pragma unroll
        for (int mi = 0; mi < 4; mi++) {
            int r = wm * 64 + mi * 16 + qr;
            RED[wn * 256 + r * 2]            = s1a[mi][0];
            RED[wn * 256 + r * 2 + 1]        = s2a[mi][0];
            RED[wn * 256 + (r + 8) * 2]      = s1a[mi][1];
            RED[wn * 256 + (r + 8) * 2 + 1]  = s2a[mi][1];
        }
    }
    __syncthreads();
    if (t < 128) {
        float s1 = RED[t * 2]     + RED[256 + t * 2]     + RED[512 + t * 2]     + RED[768 + t * 2];
        float s2 = RED[t * 2 + 1] + RED[256 + t * 2 + 1] + RED[512 + t * 2 + 1] + RED[768 + t * 2 + 1];
        out[row0 + t] = 5.0f * s1 + s2;
    }
}

// ===========================================================================
__global__ void softmax_k(const float* __restrict__ score_e, const float* __restrict__ score_t,
                          float* __restrict__ attn_e, float* __restrict__ attn_t)
{
    int b = blockIdx.x & 127;
    int wh = blockIdx.x >> 7;
    const float* src = (wh ? score_t : score_e) + b * 512;
    float* dst = (wh ? attn_t : attn_e) + b * 512;
    int t = threadIdx.x;
    float v0 = src[t], v1 = src[t + 256];
    __shared__ float red[256];
    red[t] = fmaxf(v0, v1);
    __syncthreads();
    for (int s = 128; s > 0; s >>= 1) {
        if (t < s) red[t] = fmaxf(red[t], red[t + s]);
        __syncthreads();
    }
    float mx = red[0];
    __syncthreads();
    float e0 = expf(v0 - mx), e1 = expf(v1 - mx);
    red[t] = e0 + e1;
    __syncthreads();
    for (int s = 128; s > 0; s >>= 1) {
        if (t < s) red[t] += red[t + s];
        __syncthreads();
    }
    float inv = 1.f / red[0];
    dst[t] = e0 * inv;
    dst[t + 256] = e1 * inv;
}

// contexts from the fp16 copy of static_hidden; half2 loads, 128B/warp.
__global__ void __launch_bounds__(128)
context_k(const __half2* __restrict__ sh2,
          const float* __restrict__ ae, const float* __restrict__ at,
          float* __restrict__ ce, float* __restrict__ ct)
{
    int b = blockIdx.x >> 1;
    int half = blockIdx.x & 1;
    int t = threadIdx.x;                     // 128
    __shared__ float sae[512], sat[512];
    for (int i = t; i < 512; i += 128) {
        sae[i] = ae[b * 512 + i];
        sat[i] = at[b * 512 + i];
    }
    __syncthreads();
    int h2 = half * 128 + t;                 // 0..255 half2-index
    const __half2* Sb = sh2 + (size_t)b * 131072 + h2;
    float se0 = 0.f, se1 = 0.f, st0 = 0.f, st1 = 0.f;
#pragma unroll 16
    for (int n = 0; n < 512; n++) {
        float2 f = __half22float2(Sb[(size_t)n * 256]);
        float a = sae[n], tt = sat[n];
        se0 += a * f.x;  se1 += a * f.y;
        st0 += tt * f.x; st1 += tt * f.y;
    }
    ce[b * 512 + h2 * 2]     = se0;
    ce[b * 512 + h2 * 2 + 1] = se1;
    ct[b * 512 + h2 * 2]     = st0;
    ct[b * 512 + h2 * 2 + 1] = st1;
}

// ===========================================================================
extern "C" void kernel_launch(void* const* d_in, const int* in_sizes, int n_in,
                              void* d_out, int out_size)
{
    const float* stat = (const float*)d_in[0];   // (128,512,512)
    const float* semb = (const float*)d_in[1];   // (128,1,512)
    const float* dech = (const float*)d_in[2];   // (128,1,512)
    const float* tgth = (const float*)d_in[3];   // (128,1,512)
    const float* lhh  = (const float*)d_in[4];   // (1,128,512)
    const float* ptrv = (const float*)d_in[5];   // (1,1,512)
    const float* ptrW = (const float*)d_in[6];   // (1,512,1536)
    const float* encv = (const float*)d_in[7];   // (1,1,512)
    const float* encW = (const float*)d_in[8];   // (1,512,1024)
    const float* tgtv = (const float*)d_in[9];   // (1,1,512)
    const float* tgtW = (const float*)d_in[10];  // (1,512,1024)
    const float* wih  = (const float*)d_in[11];  // (1536,512)
    const float* whh  = (const float*)d_in[12];  // (1536,512)
    const float* bih  = (const float*)d_in[13];
    const float* bhh  = (const float*)d_in[14];
    float* out = (float*)d_out;

    unsigned char* base = nullptr;
    cudaGetSymbolAddress((void**)&base, g_scratch);
    __half* sh = (__half*)(base + OFF_SH);
    __half* bhp = (__half*)(base + OFF_BH);
    float* FL = (float*)(base + OFF_FL);
    float* gx     = FL + FO_GX;
    float* gh     = FL + FO_GH;
    float* hnew   = FL + FO_HNEW;
    float* denc   = FL + FO_DENC;
    float* dtgt   = FL + FO_DTGT;
    float* sstate = FL + FO_SSTATE;
    float* cptr   = FL + FO_CPTR;
    float* ctptr  = FL + FO_CTPTR;
    float* ctxe   = FL + FO_CTXE;
    float* ctxt   = FL + FO_CTXT;
    float* sc_e   = FL + FO_SCE;
    float* sc_t   = FL + FO_SCT;
    float* at_e   = FL + FO_ATE;
    float* at_t   = FL + FO_ATT;

    // Attribute cache: set once on the (uncaptured) correctness call.
    static bool attr_done = false;
    if (!attr_done) {
        cudaFuncSetAttribute(big_mma_et_k, cudaFuncAttributeMaxDynamicSharedMemorySize,
                             SMEM_ET);
        cudaFuncSetAttribute(big_mma_ptr_k, cudaFuncAttributeMaxDynamicSharedMemorySize,
                             SMEM_PTR);
        attr_done = true;
    }

    // conversions
    convert_w_k<<<768, 256>>>(encW, tgtW, ptrW, (__half2*)bhp);
    convert_stat_k<<<32768, 256>>>(stat, (__half2*)sh);

    // GRU input/hidden GEMMs (z-batched)
    small_gemm3_k<<<dim3(24, 4, 2), 256>>>(
        dech, wih, 512, 0, gx, 1536,
        lhh,  whh, 512, 0, gh, 1536,
        lhh,  whh, 512, 0, gh, 1536);
    gru_gates_k<<<256, 256>>>(gx, gh, bih, bhh, lhh, hnew, out + 65536);

    // per-batch bias projections (z-batched)
    small_gemm3_k<<<dim3(8, 4, 3), 256>>>(
        hnew, encW, 1024, 512,  denc,   512,
        tgth, tgtW, 1024, 512,  dtgt,   512,
        semb, ptrW, 1536, 1024, sstate, 512);

    // enc/tgt GEMM -> scores
    big_mma_et_k<<<dim3(2, 512), 256, SMEM_ET>>>(sh, bhp, denc, dtgt,
                                                 encv, tgtv, sc_e, sc_t);

    // softmax + contexts + context projections
    softmax_k<<<256, 256>>>(sc_e, sc_t, at_e, at_t);
    context_k<<<256, 128>>>((const __half2*)sh, at_e, at_t, ctxe, ctxt);
    small_gemm3_k<<<dim3(8, 4, 2), 256>>>(
        ctxe, ptrW, 1536, 512, cptr,  512,
        ctxt, ptrW, 1536, 512, ctptr, 512,
        ctxt, ptrW, 1536, 512, ctptr, 512);

    // ptr GEMM with fused final pointer-score epilogue -> probs
    big_mma_ptr_k<<<512, 256, SMEM_PTR>>>(sh, bhp, cptr, ctptr, sstate, ptrv, out);
}